// round 1
// baseline (speedup 1.0000x reference)
#include <cuda_runtime.h>
#include <math.h>

// ---------------------------------------------------------------------------
// Problem constants (hardcoded from reference: B=4, T_B=2048, Q_LEN=801)
// ---------------------------------------------------------------------------
namespace {
constexpr int B_   = 4;
constexpr int H_   = 16;
constexpr int HD_  = 64;
constexpr int E_   = 1024;   // embed dim
constexpr int QL_  = 801;
constexpr int TB_  = 2048;
constexpr int T_   = 2049;   // prompt + x_b
constexpr int KD_  = 1024;   // inner dim of projections
constexpr int NPE_ = 50;     // distinct pe rows used by pos_long (full_b_step)
constexpr int KSPLIT_ = 8;   // k-splits for the tiny pos GEMM
}

// Scratch (device globals; no allocation allowed in kernel_launch)
__device__ float g_kv [(size_t)B_ * T_ * E_];   // (B*T, E) kv inputs
__device__ float g_K  [(size_t)B_ * T_ * E_];   // (B*T, E) K projection
__device__ float g_V  [(size_t)B_ * T_ * E_];   // (B*T, E) V projection
__device__ float g_p50[(size_t)NPE_ * E_];      // 50 distinct pos projections
__device__ float g_p50p[(size_t)KSPLIT_ * NPE_ * E_]; // k-split partials

// ---------------------------------------------------------------------------
// Kernel 1: kv[b,t,:] = (t==0) ? prompt : x_b[b,t-1] + pe[t-1]
// ---------------------------------------------------------------------------
__global__ void __launch_bounds__(256) build_kv_kernel(
    const float* __restrict__ xb, const float* __restrict__ prompt,
    const float* __restrict__ pe)
{
    long i = (long)blockIdx.x * blockDim.x + threadIdx.x;   // float4 index
    const long total = (long)B_ * T_ * (E_ / 4);
    if (i >= total) return;
    int  c4 = (int)(i % (E_ / 4));
    long bt = i / (E_ / 4);
    int  t  = (int)(bt % T_);
    int  b  = (int)(bt / T_);
    float4 r;
    if (t == 0) {
        r = reinterpret_cast<const float4*>(prompt)[c4];
    } else {
        float4 x = reinterpret_cast<const float4*>(xb)[((long)b * TB_ + (t - 1)) * (E_ / 4) + c4];
        float4 p = reinterpret_cast<const float4*>(pe)[(long)(t - 1) * (E_ / 4) + c4];
        r.x = x.x + p.x; r.y = x.y + p.y; r.z = x.z + p.z; r.w = x.w + p.w;
    }
    reinterpret_cast<float4*>(g_kv)[i] = r;
}

// ---------------------------------------------------------------------------
// Kernel 2: NT GEMM  C[m,n] = sum_c A[m,c] * W[n,c]   (A: MxKD, W: 1024xKD)
// 128x128x16 tiles, 256 threads, 8x8 per thread (split 4+4 for conflict-free LDS)
// ---------------------------------------------------------------------------
__global__ void __launch_bounds__(256) gemm_nt_kernel(
    const float* __restrict__ A, const float* __restrict__ W,
    float* __restrict__ C, int M)
{
    constexpr int BK = 16;
    __shared__ float As[BK][128 + 4];
    __shared__ float Ws[BK][128 + 4];

    const int tid  = threadIdx.x;
    const int tx   = tid & 15, ty = tid >> 4;
    const int lrow = tid >> 2, lseg = tid & 3;
    const int m0   = blockIdx.y * 128, n0 = blockIdx.x * 128;

    float acc[8][8];
#pragma unroll
    for (int i = 0; i < 8; i++)
#pragma unroll
        for (int j = 0; j < 8; j++) acc[i][j] = 0.f;

    for (int c0 = 0; c0 < KD_; c0 += BK) {
        const int cc = c0 + lseg * 4;
        float4 a0 = make_float4(0.f, 0.f, 0.f, 0.f);
        float4 a1 = make_float4(0.f, 0.f, 0.f, 0.f);
        if (m0 + lrow      < M) a0 = *reinterpret_cast<const float4*>(&A[(long)(m0 + lrow)      * KD_ + cc]);
        if (m0 + lrow + 64 < M) a1 = *reinterpret_cast<const float4*>(&A[(long)(m0 + lrow + 64) * KD_ + cc]);
        float4 w0 = *reinterpret_cast<const float4*>(&W[(long)(n0 + lrow)      * KD_ + cc]);
        float4 w1 = *reinterpret_cast<const float4*>(&W[(long)(n0 + lrow + 64) * KD_ + cc]);
        __syncthreads();
        As[lseg*4+0][lrow]      = a0.x; As[lseg*4+1][lrow]      = a0.y;
        As[lseg*4+2][lrow]      = a0.z; As[lseg*4+3][lrow]      = a0.w;
        As[lseg*4+0][lrow + 64] = a1.x; As[lseg*4+1][lrow + 64] = a1.y;
        As[lseg*4+2][lrow + 64] = a1.z; As[lseg*4+3][lrow + 64] = a1.w;
        Ws[lseg*4+0][lrow]      = w0.x; Ws[lseg*4+1][lrow]      = w0.y;
        Ws[lseg*4+2][lrow]      = w0.z; Ws[lseg*4+3][lrow]      = w0.w;
        Ws[lseg*4+0][lrow + 64] = w1.x; Ws[lseg*4+1][lrow + 64] = w1.y;
        Ws[lseg*4+2][lrow + 64] = w1.z; Ws[lseg*4+3][lrow + 64] = w1.w;
        __syncthreads();
#pragma unroll
        for (int kk = 0; kk < BK; kk++) {
            float4 aA = *reinterpret_cast<const float4*>(&As[kk][ty * 4]);
            float4 aB = *reinterpret_cast<const float4*>(&As[kk][64 + ty * 4]);
            float4 wA = *reinterpret_cast<const float4*>(&Ws[kk][tx * 4]);
            float4 wB = *reinterpret_cast<const float4*>(&Ws[kk][64 + tx * 4]);
            float ar[8] = {aA.x, aA.y, aA.z, aA.w, aB.x, aB.y, aB.z, aB.w};
            float wr[8] = {wA.x, wA.y, wA.z, wA.w, wB.x, wB.y, wB.z, wB.w};
#pragma unroll
            for (int i = 0; i < 8; i++)
#pragma unroll
                for (int j = 0; j < 8; j++) acc[i][j] += ar[i] * wr[j];
        }
    }
#pragma unroll
    for (int i = 0; i < 8; i++) {
        int m = m0 + (i >> 2) * 64 + ty * 4 + (i & 3);
        if (m < M) {
            *reinterpret_cast<float4*>(&C[(long)m * E_ + n0 + tx * 4]) =
                make_float4(acc[i][0], acc[i][1], acc[i][2], acc[i][3]);
            *reinterpret_cast<float4*>(&C[(long)m * E_ + n0 + 64 + tx * 4]) =
                make_float4(acc[i][4], acc[i][5], acc[i][6], acc[i][7]);
        }
    }
}

// ---------------------------------------------------------------------------
// Kernel 3: tiny pos GEMM, k-split x8: partial[ks][r,n] = sum_{c in split} pe[r,c]*Wpos[n,c]
// grid (16 n-tiles, 8 k-splits), 64x64 tile, 4x4 per thread
// ---------------------------------------------------------------------------
__global__ void __launch_bounds__(256) gemm_pos_kernel(
    const float* __restrict__ pe, const float* __restrict__ Wpos)
{
    constexpr int BK = 16, KS = KD_ / KSPLIT_;   // 128 K per split
    __shared__ float As[BK][64 + 4];
    __shared__ float Ws[BK][64 + 4];
    const int tid  = threadIdx.x;
    const int tx   = tid & 15, ty = tid >> 4;
    const int lrow = tid >> 2, lseg = tid & 3;
    const int n0   = blockIdx.x * 64;
    const int k0   = blockIdx.y * KS;

    float acc[4][4] = {};
    for (int c0 = k0; c0 < k0 + KS; c0 += BK) {
        const int cc = c0 + lseg * 4;
        float4 a = make_float4(0.f, 0.f, 0.f, 0.f);
        if (lrow < NPE_) a = *reinterpret_cast<const float4*>(&pe[(long)lrow * KD_ + cc]);
        float4 w = *reinterpret_cast<const float4*>(&Wpos[(long)(n0 + lrow) * KD_ + cc]);
        __syncthreads();
        As[lseg*4+0][lrow] = a.x; As[lseg*4+1][lrow] = a.y;
        As[lseg*4+2][lrow] = a.z; As[lseg*4+3][lrow] = a.w;
        Ws[lseg*4+0][lrow] = w.x; Ws[lseg*4+1][lrow] = w.y;
        Ws[lseg*4+2][lrow] = w.z; Ws[lseg*4+3][lrow] = w.w;
        __syncthreads();
#pragma unroll
        for (int kk = 0; kk < BK; kk++) {
            float4 a4 = *reinterpret_cast<const float4*>(&As[kk][ty * 4]);
            float4 w4 = *reinterpret_cast<const float4*>(&Ws[kk][tx * 4]);
            acc[0][0] += a4.x*w4.x; acc[0][1] += a4.x*w4.y; acc[0][2] += a4.x*w4.z; acc[0][3] += a4.x*w4.w;
            acc[1][0] += a4.y*w4.x; acc[1][1] += a4.y*w4.y; acc[1][2] += a4.y*w4.z; acc[1][3] += a4.y*w4.w;
            acc[2][0] += a4.z*w4.x; acc[2][1] += a4.z*w4.y; acc[2][2] += a4.z*w4.z; acc[2][3] += a4.z*w4.w;
            acc[3][0] += a4.w*w4.x; acc[3][1] += a4.w*w4.y; acc[3][2] += a4.w*w4.z; acc[3][3] += a4.w*w4.w;
        }
    }
#pragma unroll
    for (int ii = 0; ii < 4; ii++) {
        int m = ty * 4 + ii;
        if (m < NPE_) {
            *reinterpret_cast<float4*>(
                &g_p50p[((long)blockIdx.y * NPE_ + m) * E_ + n0 + tx * 4]) =
                make_float4(acc[ii][0], acc[ii][1], acc[ii][2], acc[ii][3]);
        }
    }
}

__global__ void __launch_bounds__(256) reduce_pos_kernel() {
    int i = blockIdx.x * 256 + threadIdx.x;          // float4 index
    const int total = NPE_ * (E_ / 4);
    if (i >= total) return;
    float4 s = make_float4(0.f, 0.f, 0.f, 0.f);
#pragma unroll
    for (int ks = 0; ks < KSPLIT_; ks++) {
        float4 v = reinterpret_cast<const float4*>(g_p50p)[(long)ks * total + i];
        s.x += v.x; s.y += v.y; s.z += v.z; s.w += v.w;
    }
    reinterpret_cast<float4*>(g_p50)[i] = s;
}

// ---------------------------------------------------------------------------
// Kernel 4: flash attention. One block = (b, h, 64-row q tile).
// Q pre-scaled by (1/8)*log2(e) so softmax is pure exp2.
// ---------------------------------------------------------------------------
__global__ void __launch_bounds__(256) flash_kernel(
    const float* __restrict__ dbg, const float* __restrict__ gates,
    float* __restrict__ out)
{
    extern __shared__ float sm[];
    float* Qt  = sm;               // [64 d][68] transposed, pre-scaled
    float* Kt  = Qt + 64 * 68;     // [64 d][68] transposed
    float* Vs  = Kt + 64 * 68;     // [64 j][68] natural
    float* Ps  = Vs + 64 * 68;     // [64 i][68] scores / probs
    float* m_s = Ps + 64 * 68;     // [64]
    float* l_s = m_s + 64;         // [64]
    float* c_s = l_s + 64;         // [64]

    const int tid  = threadIdx.x;
    const int tx   = tid & 15, ty = tid >> 4;
    const int lrow = tid >> 2, lseg = tid & 3;
    const int q0 = blockIdx.x * 64;
    const int h  = blockIdx.y;
    const int b  = blockIdx.z;
    const float QSC = 0.125f * 1.4426950408889634f;   // 1/sqrt(64) * log2(e)

    // ---- load Q tile (debug + pos proj), transposed + scaled ----
    {
        const int p = q0 + lrow;
        if (p < QL_) {
            const int pidx = (p * NPE_) / QL_;
            const float* dq = &dbg[(((long)(b * H_ + h) * QL_) + p) * HD_];
            const float* pp = &g_p50[(long)pidx * E_ + h * HD_];
#pragma unroll
            for (int w = 0; w < 4; w++) {
                const int d0 = (lseg + 4 * w) * 4;
                float4 dv = *reinterpret_cast<const float4*>(&dq[d0]);
                float4 pv = *reinterpret_cast<const float4*>(&pp[d0]);
                Qt[(d0 + 0) * 68 + lrow] = (dv.x + pv.x) * QSC;
                Qt[(d0 + 1) * 68 + lrow] = (dv.y + pv.y) * QSC;
                Qt[(d0 + 2) * 68 + lrow] = (dv.z + pv.z) * QSC;
                Qt[(d0 + 3) * 68 + lrow] = (dv.w + pv.w) * QSC;
            }
        } else {
#pragma unroll
            for (int w = 0; w < 4; w++) {
                const int d0 = (lseg + 4 * w) * 4;
                Qt[(d0 + 0) * 68 + lrow] = 0.f; Qt[(d0 + 1) * 68 + lrow] = 0.f;
                Qt[(d0 + 2) * 68 + lrow] = 0.f; Qt[(d0 + 3) * 68 + lrow] = 0.f;
            }
        }
    }
    if (tid < 64) { m_s[tid] = -1e30f; l_s[tid] = 0.f; }
    float acc[4][4] = {};
    __syncthreads();

    for (int t0 = 0; t0 < T_; t0 += 64) {
        const int vk = (T_ - t0 < 64) ? (T_ - t0) : 64;

        // ---- load K (transposed) + V (natural) tiles ----
        {
            const int j = lrow;
            if (j < vk) {
                const float* kr = &g_K[((long)b * T_ + t0 + j) * E_ + h * HD_];
                const float* vr = &g_V[((long)b * T_ + t0 + j) * E_ + h * HD_];
#pragma unroll
                for (int w = 0; w < 4; w++) {
                    const int d0 = (lseg + 4 * w) * 4;
                    float4 kv = *reinterpret_cast<const float4*>(&kr[d0]);
                    Kt[(d0 + 0) * 68 + j] = kv.x; Kt[(d0 + 1) * 68 + j] = kv.y;
                    Kt[(d0 + 2) * 68 + j] = kv.z; Kt[(d0 + 3) * 68 + j] = kv.w;
                    *reinterpret_cast<float4*>(&Vs[j * 68 + d0]) =
                        *reinterpret_cast<const float4*>(&vr[d0]);
                }
            } else {
#pragma unroll
                for (int w = 0; w < 4; w++) {
                    const int d0 = (lseg + 4 * w) * 4;
                    Kt[(d0 + 0) * 68 + j] = 0.f; Kt[(d0 + 1) * 68 + j] = 0.f;
                    Kt[(d0 + 2) * 68 + j] = 0.f; Kt[(d0 + 3) * 68 + j] = 0.f;
                    *reinterpret_cast<float4*>(&Vs[j * 68 + d0]) =
                        make_float4(0.f, 0.f, 0.f, 0.f);
                }
            }
        }
        __syncthreads();

        // ---- GEMM1: S = Q K^T (already in log2 domain) ----
        float s[4][4] = {};
#pragma unroll 8
        for (int d = 0; d < 64; d++) {
            float4 qa = *reinterpret_cast<const float4*>(&Qt[d * 68 + ty * 4]);
            float4 ka = *reinterpret_cast<const float4*>(&Kt[d * 68 + tx * 4]);
            s[0][0] += qa.x*ka.x; s[0][1] += qa.x*ka.y; s[0][2] += qa.x*ka.z; s[0][3] += qa.x*ka.w;
            s[1][0] += qa.y*ka.x; s[1][1] += qa.y*ka.y; s[1][2] += qa.y*ka.z; s[1][3] += qa.y*ka.w;
            s[2][0] += qa.z*ka.x; s[2][1] += qa.z*ka.y; s[2][2] += qa.z*ka.z; s[2][3] += qa.z*ka.w;
            s[3][0] += qa.w*ka.x; s[3][1] += qa.w*ka.y; s[3][2] += qa.w*ka.z; s[3][3] += qa.w*ka.w;
        }
#pragma unroll
        for (int ii = 0; ii < 4; ii++) {
            *reinterpret_cast<float4*>(&Ps[(ty * 4 + ii) * 68 + tx * 4]) =
                make_float4(s[ii][0], s[ii][1], s[ii][2], s[ii][3]);
        }
        __syncthreads();

        // ---- online softmax (4 threads per row, butterfly reduce) ----
        {
            const int r = lrow, qt = lseg;
            float* prow = &Ps[r * 68 + qt * 16];
            const int lim = vk - qt * 16;   // valid count in this quarter
            float mx = -1e30f;
#pragma unroll
            for (int jj = 0; jj < 16; jj++)
                if (jj < lim) mx = fmaxf(mx, prow[jj]);
            mx = fmaxf(mx, __shfl_xor_sync(0xffffffffu, mx, 1));
            mx = fmaxf(mx, __shfl_xor_sync(0xffffffffu, mx, 2));
            const float m_old = m_s[r];
            const float m_new = fmaxf(m_old, mx);
            float sum = 0.f;
#pragma unroll
            for (int jj = 0; jj < 16; jj++) {
                float v = (jj < lim) ? exp2f(prow[jj] - m_new) : 0.f;
                prow[jj] = v;
                sum += v;
            }
            sum += __shfl_xor_sync(0xffffffffu, sum, 1);
            sum += __shfl_xor_sync(0xffffffffu, sum, 2);
            if (qt == 0) {
                const float corr = exp2f(m_old - m_new);
                l_s[r] = l_s[r] * corr + sum;
                m_s[r] = m_new;
                c_s[r] = corr;
            }
        }
        __syncthreads();

        // ---- rescale accumulators + GEMM2: O += P V ----
#pragma unroll
        for (int ii = 0; ii < 4; ii++) {
            const float c = c_s[ty * 4 + ii];
            acc[ii][0] *= c; acc[ii][1] *= c; acc[ii][2] *= c; acc[ii][3] *= c;
        }
#pragma unroll 4
        for (int j0 = 0; j0 < 64; j0 += 4) {
            float4 v0 = *reinterpret_cast<const float4*>(&Vs[(j0 + 0) * 68 + tx * 4]);
            float4 v1 = *reinterpret_cast<const float4*>(&Vs[(j0 + 1) * 68 + tx * 4]);
            float4 v2 = *reinterpret_cast<const float4*>(&Vs[(j0 + 2) * 68 + tx * 4]);
            float4 v3 = *reinterpret_cast<const float4*>(&Vs[(j0 + 3) * 68 + tx * 4]);
#pragma unroll
            for (int ii = 0; ii < 4; ii++) {
                float4 pr = *reinterpret_cast<const float4*>(&Ps[(ty * 4 + ii) * 68 + j0]);
                acc[ii][0] += pr.x*v0.x + pr.y*v1.x + pr.z*v2.x + pr.w*v3.x;
                acc[ii][1] += pr.x*v0.y + pr.y*v1.y + pr.z*v2.y + pr.w*v3.y;
                acc[ii][2] += pr.x*v0.z + pr.y*v1.z + pr.z*v2.z + pr.w*v3.z;
                acc[ii][3] += pr.x*v0.w + pr.y*v1.w + pr.z*v2.w + pr.w*v3.w;
            }
        }
        __syncthreads();
    }

    // ---- epilogue: O / l * gates → out[b, p, h*64 + d] ----
    const float g = gates[0];
#pragma unroll
    for (int ii = 0; ii < 4; ii++) {
        const int p = q0 + ty * 4 + ii;
        if (p < QL_) {
            const float inv = g / l_s[ty * 4 + ii];
            *reinterpret_cast<float4*>(&out[((long)b * QL_ + p) * E_ + h * HD_ + tx * 4]) =
                make_float4(acc[ii][0] * inv, acc[ii][1] * inv,
                            acc[ii][2] * inv, acc[ii][3] * inv);
        }
    }
}

// ---------------------------------------------------------------------------
// Launch
// ---------------------------------------------------------------------------
extern "C" void kernel_launch(void* const* d_in, const int* in_sizes, int n_in,
                              void* d_out, int out_size)
{
    const float* x_b    = (const float*)d_in[1];
    const float* dbg    = (const float*)d_in[2];
    const float* Wk     = (const float*)d_in[3];
    const float* Wv     = (const float*)d_in[4];
    const float* Wpos   = (const float*)d_in[5];
    const float* prompt = (const float*)d_in[6];
    const float* gates  = (const float*)d_in[7];
    const float* pe     = (const float*)d_in[8];
    float* out = (float*)d_out;

    float *kv_p, *K_p, *V_p;
    cudaGetSymbolAddress((void**)&kv_p, g_kv);
    cudaGetSymbolAddress((void**)&K_p,  g_K);
    cudaGetSymbolAddress((void**)&V_p,  g_V);

    // 1) kv build
    {
        const long total4 = (long)B_ * T_ * (E_ / 4);
        const int blocks = (int)((total4 + 255) / 256);
        build_kv_kernel<<<blocks, 256>>>(x_b, prompt, pe);
    }
    // 2) K/V projections
    {
        dim3 g(E_ / 128, (B_ * T_ + 127) / 128);
        gemm_nt_kernel<<<g, 256>>>(kv_p, Wk, K_p, B_ * T_);
        gemm_nt_kernel<<<g, 256>>>(kv_p, Wv, V_p, B_ * T_);
    }
    // 3) tiny pos GEMM (k-split + reduce)
    {
        dim3 g(E_ / 64, KSPLIT_);
        gemm_pos_kernel<<<g, 256>>>(pe, Wpos);
        const int total4 = NPE_ * (E_ / 4);
        reduce_pos_kernel<<<(total4 + 255) / 256, 256>>>();
    }
    // 4) flash attention
    {
        const int smem = (4 * 64 * 68 + 3 * 64) * (int)sizeof(float);
        cudaFuncSetAttribute(flash_kernel, cudaFuncAttributeMaxDynamicSharedMemorySize, smem);
        dim3 g((QL_ + 63) / 64, H_, B_);
        flash_kernel<<<g, 256, smem>>>(dbg, gates, out);
    }
}

// round 2
// speedup vs baseline: 1.0145x; 1.0145x over previous
#include <cuda_runtime.h>
#include <math.h>

// ---------------------------------------------------------------------------
// Problem constants (B=4, T_B=2048, Q_LEN=801)
// ---------------------------------------------------------------------------
namespace {
constexpr int B_   = 4;
constexpr int H_   = 16;
constexpr int HD_  = 64;
constexpr int E_   = 1024;
constexpr int QL_  = 801;
constexpr int TB_  = 2048;
constexpr int T_   = 2049;
constexpr int KD_  = 1024;
constexpr int NPE_ = 50;
constexpr int KSPLIT_ = 8;
}

// ---------------------------------------------------------------------------
// Packed fp32x2 (FFMA2) helpers — sm_103a only
// ---------------------------------------------------------------------------
typedef unsigned long long f32x2;
__device__ __forceinline__ f32x2 pk2(float lo, float hi) {
    f32x2 r; asm("mov.b64 %0, {%1, %2};" : "=l"(r) : "f"(lo), "f"(hi)); return r;
}
__device__ __forceinline__ void ffma2(f32x2& d, f32x2 a, f32x2 b) {
    asm("fma.rn.f32x2 %0, %1, %2, %3;" : "=l"(d) : "l"(a), "l"(b), "l"(d));
}
__device__ __forceinline__ f32x2 mul2(f32x2 a, f32x2 b) {
    f32x2 r; asm("mul.rn.f32x2 %0, %1, %2;" : "=l"(r) : "l"(a), "l"(b)); return r;
}
__device__ __forceinline__ float2 upk(f32x2 v) {
    float2 r; asm("mov.b64 {%0, %1}, %2;" : "=f"(r.x), "=f"(r.y) : "l"(v)); return r;
}

// Scratch
__device__ float g_kv [(size_t)B_ * T_ * E_];
__device__ float g_K  [(size_t)B_ * T_ * E_];
__device__ float g_V  [(size_t)B_ * T_ * E_];
__device__ float g_p50[(size_t)NPE_ * E_];
__device__ float g_p50p[(size_t)KSPLIT_ * NPE_ * E_];

// ---------------------------------------------------------------------------
// Kernel 1: kv build
// ---------------------------------------------------------------------------
__global__ void __launch_bounds__(256) build_kv_kernel(
    const float* __restrict__ xb, const float* __restrict__ prompt,
    const float* __restrict__ pe)
{
    long i = (long)blockIdx.x * blockDim.x + threadIdx.x;
    const long total = (long)B_ * T_ * (E_ / 4);
    if (i >= total) return;
    int  c4 = (int)(i % (E_ / 4));
    long bt = i / (E_ / 4);
    int  t  = (int)(bt % T_);
    int  b  = (int)(bt / T_);
    float4 r;
    if (t == 0) {
        r = reinterpret_cast<const float4*>(prompt)[c4];
    } else {
        float4 x = reinterpret_cast<const float4*>(xb)[((long)b * TB_ + (t - 1)) * (E_ / 4) + c4];
        float4 p = reinterpret_cast<const float4*>(pe)[(long)(t - 1) * (E_ / 4) + c4];
        r.x = x.x + p.x; r.y = x.y + p.y; r.z = x.z + p.z; r.w = x.w + p.w;
    }
    reinterpret_cast<float4*>(g_kv)[i] = r;
}

// ---------------------------------------------------------------------------
// Kernel 2: NT GEMM with packed-N FFMA2.  C[m,n] = sum_c A[m,c]*W[n,c]
// ---------------------------------------------------------------------------
__global__ void __launch_bounds__(256) gemm_nt_kernel(
    const float* __restrict__ A, const float* __restrict__ W,
    float* __restrict__ C, int M)
{
    constexpr int BK = 16;
    __shared__ float As[BK][128 + 4];
    __shared__ float Ws[BK][128 + 4];

    const int tid  = threadIdx.x;
    const int tx   = tid & 15, ty = tid >> 4;
    const int lrow = tid >> 2, lseg = tid & 3;
    const int m0   = blockIdx.y * 128, n0 = blockIdx.x * 128;

    f32x2 acc2[8][4];
#pragma unroll
    for (int i = 0; i < 8; i++)
#pragma unroll
        for (int j = 0; j < 4; j++) acc2[i][j] = pk2(0.f, 0.f);

    for (int c0 = 0; c0 < KD_; c0 += BK) {
        const int cc = c0 + lseg * 4;
        float4 a0 = make_float4(0.f, 0.f, 0.f, 0.f);
        float4 a1 = make_float4(0.f, 0.f, 0.f, 0.f);
        if (m0 + lrow      < M) a0 = *reinterpret_cast<const float4*>(&A[(long)(m0 + lrow)      * KD_ + cc]);
        if (m0 + lrow + 64 < M) a1 = *reinterpret_cast<const float4*>(&A[(long)(m0 + lrow + 64) * KD_ + cc]);
        float4 w0 = *reinterpret_cast<const float4*>(&W[(long)(n0 + lrow)      * KD_ + cc]);
        float4 w1 = *reinterpret_cast<const float4*>(&W[(long)(n0 + lrow + 64) * KD_ + cc]);
        __syncthreads();
        As[lseg*4+0][lrow]      = a0.x; As[lseg*4+1][lrow]      = a0.y;
        As[lseg*4+2][lrow]      = a0.z; As[lseg*4+3][lrow]      = a0.w;
        As[lseg*4+0][lrow + 64] = a1.x; As[lseg*4+1][lrow + 64] = a1.y;
        As[lseg*4+2][lrow + 64] = a1.z; As[lseg*4+3][lrow + 64] = a1.w;
        Ws[lseg*4+0][lrow]      = w0.x; Ws[lseg*4+1][lrow]      = w0.y;
        Ws[lseg*4+2][lrow]      = w0.z; Ws[lseg*4+3][lrow]      = w0.w;
        Ws[lseg*4+0][lrow + 64] = w1.x; Ws[lseg*4+1][lrow + 64] = w1.y;
        Ws[lseg*4+2][lrow + 64] = w1.z; Ws[lseg*4+3][lrow + 64] = w1.w;
        __syncthreads();
#pragma unroll
        for (int kk = 0; kk < BK; kk++) {
            float4 aA = *reinterpret_cast<const float4*>(&As[kk][ty * 4]);
            float4 aB = *reinterpret_cast<const float4*>(&As[kk][64 + ty * 4]);
            float4 wA = *reinterpret_cast<const float4*>(&Ws[kk][tx * 4]);
            float4 wB = *reinterpret_cast<const float4*>(&Ws[kk][64 + tx * 4]);
            f32x2 wp[4] = { pk2(wA.x, wA.y), pk2(wA.z, wA.w),
                            pk2(wB.x, wB.y), pk2(wB.z, wB.w) };
            float ar[8] = {aA.x, aA.y, aA.z, aA.w, aB.x, aB.y, aB.z, aB.w};
#pragma unroll
            for (int i = 0; i < 8; i++) {
                f32x2 as_ = pk2(ar[i], ar[i]);
#pragma unroll
                for (int j = 0; j < 4; j++) ffma2(acc2[i][j], as_, wp[j]);
            }
        }
    }
#pragma unroll
    for (int i = 0; i < 8; i++) {
        int m = m0 + (i >> 2) * 64 + ty * 4 + (i & 3);
        if (m < M) {
            float2 u0 = upk(acc2[i][0]), u1 = upk(acc2[i][1]);
            float2 u2 = upk(acc2[i][2]), u3 = upk(acc2[i][3]);
            *reinterpret_cast<float4*>(&C[(long)m * E_ + n0 + tx * 4]) =
                make_float4(u0.x, u0.y, u1.x, u1.y);
            *reinterpret_cast<float4*>(&C[(long)m * E_ + n0 + 64 + tx * 4]) =
                make_float4(u2.x, u2.y, u3.x, u3.y);
        }
    }
}

// ---------------------------------------------------------------------------
// Kernel 3: tiny pos GEMM (unchanged; 12us, negligible)
// ---------------------------------------------------------------------------
__global__ void __launch_bounds__(256) gemm_pos_kernel(
    const float* __restrict__ pe, const float* __restrict__ Wpos)
{
    constexpr int BK = 16, KS = KD_ / KSPLIT_;
    __shared__ float As[BK][64 + 4];
    __shared__ float Ws[BK][64 + 4];
    const int tid  = threadIdx.x;
    const int tx   = tid & 15, ty = tid >> 4;
    const int lrow = tid >> 2, lseg = tid & 3;
    const int n0   = blockIdx.x * 64;
    const int k0   = blockIdx.y * KS;

    float acc[4][4] = {};
    for (int c0 = k0; c0 < k0 + KS; c0 += BK) {
        const int cc = c0 + lseg * 4;
        float4 a = make_float4(0.f, 0.f, 0.f, 0.f);
        if (lrow < NPE_) a = *reinterpret_cast<const float4*>(&pe[(long)lrow * KD_ + cc]);
        float4 w = *reinterpret_cast<const float4*>(&Wpos[(long)(n0 + lrow) * KD_ + cc]);
        __syncthreads();
        As[lseg*4+0][lrow] = a.x; As[lseg*4+1][lrow] = a.y;
        As[lseg*4+2][lrow] = a.z; As[lseg*4+3][lrow] = a.w;
        Ws[lseg*4+0][lrow] = w.x; Ws[lseg*4+1][lrow] = w.y;
        Ws[lseg*4+2][lrow] = w.z; Ws[lseg*4+3][lrow] = w.w;
        __syncthreads();
#pragma unroll
        for (int kk = 0; kk < BK; kk++) {
            float4 a4 = *reinterpret_cast<const float4*>(&As[kk][ty * 4]);
            float4 w4 = *reinterpret_cast<const float4*>(&Ws[kk][tx * 4]);
            acc[0][0] += a4.x*w4.x; acc[0][1] += a4.x*w4.y; acc[0][2] += a4.x*w4.z; acc[0][3] += a4.x*w4.w;
            acc[1][0] += a4.y*w4.x; acc[1][1] += a4.y*w4.y; acc[1][2] += a4.y*w4.z; acc[1][3] += a4.y*w4.w;
            acc[2][0] += a4.z*w4.x; acc[2][1] += a4.z*w4.y; acc[2][2] += a4.z*w4.z; acc[2][3] += a4.z*w4.w;
            acc[3][0] += a4.w*w4.x; acc[3][1] += a4.w*w4.y; acc[3][2] += a4.w*w4.z; acc[3][3] += a4.w*w4.w;
        }
    }
#pragma unroll
    for (int ii = 0; ii < 4; ii++) {
        int m = ty * 4 + ii;
        if (m < NPE_) {
            *reinterpret_cast<float4*>(
                &g_p50p[((long)blockIdx.y * NPE_ + m) * E_ + n0 + tx * 4]) =
                make_float4(acc[ii][0], acc[ii][1], acc[ii][2], acc[ii][3]);
        }
    }
}

__global__ void __launch_bounds__(256) reduce_pos_kernel() {
    int i = blockIdx.x * 256 + threadIdx.x;
    const int total = NPE_ * (E_ / 4);
    if (i >= total) return;
    float4 s = make_float4(0.f, 0.f, 0.f, 0.f);
#pragma unroll
    for (int ks = 0; ks < KSPLIT_; ks++) {
        float4 v = reinterpret_cast<const float4*>(g_p50p)[(long)ks * total + i];
        s.x += v.x; s.y += v.y; s.z += v.z; s.w += v.w;
    }
    reinterpret_cast<float4*>(g_p50)[i] = s;
}

// ---------------------------------------------------------------------------
// Kernel 4: flash attention with FFMA2-packed GEMMs.
//   Qp/Kp: f32x2[32][PADQ]  — pairs along d (head dim), indexed [d2][row/col]
//   Vpj:   f32x2[64][PADV]  — pairs along j (kv row), indexed [d][j2]
//   Ps:    float[64][PADP]  — probabilities
// Thread (tx,ty) owns rows ty+16*ii, cols tx+16*jj (ii,jj = 0..3).
// Softmax state (m,l) lives in registers, replicated across each 16-lane row
// group via shfl_xor reduction.
// ---------------------------------------------------------------------------
namespace {
constexpr int PADQ = 65;   // f32x2 stride for Qp/Kp rows
constexpr int PADV = 33;   // f32x2 stride for Vpj rows
constexpr int PADP = 68;   // float stride for Ps rows (even -> 8B aligned pairs)
constexpr int SMEM_FLASH = (2 * 32 * PADQ + 64 * PADV) * 8 + 64 * PADP * 4;
}

__global__ void __launch_bounds__(256) flash_kernel(
    const float* __restrict__ dbg, const float* __restrict__ gates,
    float* __restrict__ out)
{
    extern __shared__ char smraw[];
    f32x2* Qp  = reinterpret_cast<f32x2*>(smraw);
    f32x2* Kp  = Qp + 32 * PADQ;
    f32x2* Vpj = Kp + 32 * PADQ;
    float* Ps  = reinterpret_cast<float*>(Vpj + 64 * PADV);

    const int tid  = threadIdx.x;
    const int tx   = tid & 15, ty = tid >> 4;
    const int lrow = tid >> 2, lseg = tid & 3;
    const int q0 = blockIdx.x * 64;
    const int h  = blockIdx.y;
    const int b  = blockIdx.z;
    const float QSC = 0.125f * 1.4426950408889634f;   // 1/sqrt(64) * log2(e)

    // ---- load Q tile into d-pair-packed layout, pre-scaled ----
    {
        const int p = q0 + lrow;
        if (p < QL_) {
            const int pidx = (p * NPE_) / QL_;
            const float* dq = &dbg[(((long)(b * H_ + h) * QL_) + p) * HD_];
            const float* pp = &g_p50[(long)pidx * E_ + h * HD_];
#pragma unroll
            for (int w = 0; w < 4; w++) {
                const int d0 = (lseg + 4 * w) * 4;
                float4 dv = *reinterpret_cast<const float4*>(&dq[d0]);
                float4 pv = *reinterpret_cast<const float4*>(&pp[d0]);
                Qp[(d0 >> 1) * PADQ + lrow]       = pk2((dv.x + pv.x) * QSC, (dv.y + pv.y) * QSC);
                Qp[((d0 >> 1) + 1) * PADQ + lrow] = pk2((dv.z + pv.z) * QSC, (dv.w + pv.w) * QSC);
            }
        } else {
#pragma unroll
            for (int w = 0; w < 4; w++) {
                const int d0 = (lseg + 4 * w) * 4;
                Qp[(d0 >> 1) * PADQ + lrow]       = 0ull;
                Qp[((d0 >> 1) + 1) * PADQ + lrow] = 0ull;
            }
        }
    }

    float mst[4], lst[4];
#pragma unroll
    for (int ii = 0; ii < 4; ii++) { mst[ii] = -1e30f; lst[ii] = 0.f; }
    f32x2 acc2[4][4];
#pragma unroll
    for (int ii = 0; ii < 4; ii++)
#pragma unroll
        for (int jj = 0; jj < 4; jj++) acc2[ii][jj] = 0ull;

    for (int t0 = 0; t0 < T_; t0 += 64) {
        const int vk = (T_ - t0 < 64) ? (T_ - t0) : 64;

        // ---- load K (d-pair-packed) + V (j-pair-packed transposed) ----
        {
            const int j = lrow;
            float* Vf = reinterpret_cast<float*>(Vpj);
            if (j < vk) {
                const float* kr = &g_K[((long)b * T_ + t0 + j) * E_ + h * HD_];
                const float* vr = &g_V[((long)b * T_ + t0 + j) * E_ + h * HD_];
                const int vo = 2 * (j >> 1) + (j & 1);
#pragma unroll
                for (int w = 0; w < 4; w++) {
                    const int d0 = (lseg + 4 * w) * 4;
                    float4 kv4 = *reinterpret_cast<const float4*>(&kr[d0]);
                    Kp[(d0 >> 1) * PADQ + j]       = pk2(kv4.x, kv4.y);
                    Kp[((d0 >> 1) + 1) * PADQ + j] = pk2(kv4.z, kv4.w);
                    float4 vv4 = *reinterpret_cast<const float4*>(&vr[d0]);
                    Vf[(d0 + 0) * 2 * PADV + vo] = vv4.x;
                    Vf[(d0 + 1) * 2 * PADV + vo] = vv4.y;
                    Vf[(d0 + 2) * 2 * PADV + vo] = vv4.z;
                    Vf[(d0 + 3) * 2 * PADV + vo] = vv4.w;
                }
            } else {
                const int vo = 2 * (j >> 1) + (j & 1);
#pragma unroll
                for (int w = 0; w < 4; w++) {
                    const int d0 = (lseg + 4 * w) * 4;
                    Kp[(d0 >> 1) * PADQ + j]       = 0ull;
                    Kp[((d0 >> 1) + 1) * PADQ + j] = 0ull;
                    Vf[(d0 + 0) * 2 * PADV + vo] = 0.f;
                    Vf[(d0 + 1) * 2 * PADV + vo] = 0.f;
                    Vf[(d0 + 2) * 2 * PADV + vo] = 0.f;
                    Vf[(d0 + 3) * 2 * PADV + vo] = 0.f;
                }
            }
        }
        __syncthreads();

        // ---- GEMM1: S = Q K^T  (packed along d; lanes = d even/odd partials)
        f32x2 s2[4][4];
#pragma unroll
        for (int ii = 0; ii < 4; ii++)
#pragma unroll
            for (int jj = 0; jj < 4; jj++) s2[ii][jj] = 0ull;
#pragma unroll 4
        for (int d2 = 0; d2 < 32; d2++) {
            f32x2 qv[4], kv[4];
#pragma unroll
            for (int ii = 0; ii < 4; ii++) qv[ii] = Qp[d2 * PADQ + ty + 16 * ii];
#pragma unroll
            for (int jj = 0; jj < 4; jj++) kv[jj] = Kp[d2 * PADQ + tx + 16 * jj];
#pragma unroll
            for (int ii = 0; ii < 4; ii++)
#pragma unroll
                for (int jj = 0; jj < 4; jj++) ffma2(s2[ii][jj], qv[ii], kv[jj]);
        }

        // combine packed partials -> scores (log2 domain)
        float s[4][4];
#pragma unroll
        for (int ii = 0; ii < 4; ii++)
#pragma unroll
            for (int jj = 0; jj < 4; jj++) {
                float2 u = upk(s2[ii][jj]);
                s[ii][jj] = u.x + u.y;
            }

        // ---- online softmax per row (16-lane row groups) ----
#pragma unroll
        for (int ii = 0; ii < 4; ii++) {
            const int r = ty + 16 * ii;
            float mx = -1e30f;
#pragma unroll
            for (int jj = 0; jj < 4; jj++)
                if (tx + 16 * jj < vk) mx = fmaxf(mx, s[ii][jj]);
            mx = fmaxf(mx, __shfl_xor_sync(0xffffffffu, mx, 1));
            mx = fmaxf(mx, __shfl_xor_sync(0xffffffffu, mx, 2));
            mx = fmaxf(mx, __shfl_xor_sync(0xffffffffu, mx, 4));
            mx = fmaxf(mx, __shfl_xor_sync(0xffffffffu, mx, 8));
            const float m_new = fmaxf(mst[ii], mx);
            const float corr = exp2f(mst[ii] - m_new);
            float sum = 0.f;
            float p[4];
#pragma unroll
            for (int jj = 0; jj < 4; jj++) {
                p[jj] = (tx + 16 * jj < vk) ? exp2f(s[ii][jj] - m_new) : 0.f;
                sum += p[jj];
            }
            sum += __shfl_xor_sync(0xffffffffu, sum, 1);
            sum += __shfl_xor_sync(0xffffffffu, sum, 2);
            sum += __shfl_xor_sync(0xffffffffu, sum, 4);
            sum += __shfl_xor_sync(0xffffffffu, sum, 8);
            lst[ii] = lst[ii] * corr + sum;
            mst[ii] = m_new;
            // rescale packed accumulators
            const f32x2 c2 = pk2(corr, corr);
#pragma unroll
            for (int jj = 0; jj < 4; jj++) acc2[ii][jj] = mul2(acc2[ii][jj], c2);
            // store probs
#pragma unroll
            for (int jj = 0; jj < 4; jj++) Ps[r * PADP + tx + 16 * jj] = p[jj];
        }
        __syncthreads();

        // ---- GEMM2: O += P V  (packed along j; lanes = j even/odd partials)
#pragma unroll 4
        for (int j2 = 0; j2 < 32; j2++) {
            f32x2 pv[4], vv[4];
#pragma unroll
            for (int ii = 0; ii < 4; ii++)
                pv[ii] = *reinterpret_cast<const f32x2*>(&Ps[(ty + 16 * ii) * PADP + 2 * j2]);
#pragma unroll
            for (int jj = 0; jj < 4; jj++) vv[jj] = Vpj[(tx + 16 * jj) * PADV + j2];
#pragma unroll
            for (int ii = 0; ii < 4; ii++)
#pragma unroll
                for (int jj = 0; jj < 4; jj++) ffma2(acc2[ii][jj], pv[ii], vv[jj]);
        }
        __syncthreads();
    }

    // ---- epilogue ----
    const float g = gates[0];
#pragma unroll
    for (int ii = 0; ii < 4; ii++) {
        const int p = q0 + ty + 16 * ii;
        if (p < QL_) {
            const float inv = g / lst[ii];
            float* orow = &out[((long)b * QL_ + p) * E_ + h * HD_];
#pragma unroll
            for (int jj = 0; jj < 4; jj++) {
                float2 u = upk(acc2[ii][jj]);
                orow[tx + 16 * jj] = (u.x + u.y) * inv;
            }
        }
    }
}

// ---------------------------------------------------------------------------
// Launch
// ---------------------------------------------------------------------------
extern "C" void kernel_launch(void* const* d_in, const int* in_sizes, int n_in,
                              void* d_out, int out_size)
{
    const float* x_b    = (const float*)d_in[1];
    const float* dbg    = (const float*)d_in[2];
    const float* Wk     = (const float*)d_in[3];
    const float* Wv     = (const float*)d_in[4];
    const float* Wpos   = (const float*)d_in[5];
    const float* prompt = (const float*)d_in[6];
    const float* gates  = (const float*)d_in[7];
    const float* pe     = (const float*)d_in[8];
    float* out = (float*)d_out;

    float *kv_p, *K_p, *V_p;
    cudaGetSymbolAddress((void**)&kv_p, g_kv);
    cudaGetSymbolAddress((void**)&K_p,  g_K);
    cudaGetSymbolAddress((void**)&V_p,  g_V);

    {
        const long total4 = (long)B_ * T_ * (E_ / 4);
        const int blocks = (int)((total4 + 255) / 256);
        build_kv_kernel<<<blocks, 256>>>(x_b, prompt, pe);
    }
    {
        dim3 g(E_ / 128, (B_ * T_ + 127) / 128);
        gemm_nt_kernel<<<g, 256>>>(kv_p, Wk, K_p, B_ * T_);
        gemm_nt_kernel<<<g, 256>>>(kv_p, Wv, V_p, B_ * T_);
    }
    {
        dim3 g(E_ / 64, KSPLIT_);
        gemm_pos_kernel<<<g, 256>>>(pe, Wpos);
        const int total4 = NPE_ * (E_ / 4);
        reduce_pos_kernel<<<(total4 + 255) / 256, 256>>>();
    }
    {
        cudaFuncSetAttribute(flash_kernel, cudaFuncAttributeMaxDynamicSharedMemorySize, SMEM_FLASH);
        dim3 g((QL_ + 63) / 64, H_, B_);
        flash_kernel<<<g, 256, SMEM_FLASH>>>(dbg, gates, out);
    }
}

// round 4
// speedup vs baseline: 1.4132x; 1.3930x over previous
#include <cuda_runtime.h>
#include <cuda_bf16.h>
#include <math.h>
#include <stdint.h>

// ---------------------------------------------------------------------------
// Problem constants (B=4, T_B=2048, Q_LEN=801)
// ---------------------------------------------------------------------------
namespace {
constexpr int B_   = 4;
constexpr int H_   = 16;
constexpr int HD_  = 64;
constexpr int E_   = 1024;
constexpr int QL_  = 801;
constexpr int TB_  = 2048;
constexpr int T_   = 2049;
constexpr int KD_  = 1024;
constexpr int NPE_ = 50;
constexpr int KSPLIT_ = 8;
constexpr int M_KV  = B_ * T_;           // 8196
constexpr int MPAD  = 8320;              // 65 * 128
}

// ---------------------------------------------------------------------------
// Packed fp32x2 helpers (flash kernel)
// ---------------------------------------------------------------------------
typedef unsigned long long f32x2;
__device__ __forceinline__ f32x2 pk2(float lo, float hi) {
    f32x2 r; asm("mov.b64 %0, {%1, %2};" : "=l"(r) : "f"(lo), "f"(hi)); return r;
}
__device__ __forceinline__ void ffma2(f32x2& d, f32x2 a, f32x2 b) {
    asm("fma.rn.f32x2 %0, %1, %2, %3;" : "=l"(d) : "l"(a), "l"(b), "l"(d));
}
__device__ __forceinline__ f32x2 mul2(f32x2 a, f32x2 b) {
    f32x2 r; asm("mul.rn.f32x2 %0, %1, %2;" : "=l"(r) : "l"(a), "l"(b)); return r;
}
__device__ __forceinline__ float2 upk(f32x2 v) {
    float2 r; asm("mov.b64 {%0, %1}, %2;" : "=f"(r.x), "=f"(r.y) : "l"(v)); return r;
}

// ---------------------------------------------------------------------------
// Device scratch
// ---------------------------------------------------------------------------
__device__ float g_K  [(size_t)B_ * T_ * E_];
__device__ float g_V  [(size_t)B_ * T_ * E_];
__device__ float g_p50[(size_t)NPE_ * E_];
__device__ float g_p50p[(size_t)KSPLIT_ * NPE_ * E_];
__device__ __nv_bfloat16 g_Ah[(size_t)MPAD * KD_];
__device__ __nv_bfloat16 g_Al[(size_t)MPAD * KD_];
__device__ __nv_bfloat16 g_Wh[(size_t)2 * KD_ * KD_];
__device__ __nv_bfloat16 g_Wl[(size_t)2 * KD_ * KD_];

// ---------------------------------------------------------------------------
// Helpers (family-portable only: cp.async, ldmatrix, mma.sync)
// ---------------------------------------------------------------------------
__device__ __forceinline__ uint32_t smem_u32(const void* p) {
    uint32_t a;
    asm("{ .reg .u64 t; cvta.to.shared.u64 t, %1; cvt.u32.u64 %0, t; }" : "=r"(a) : "l"(p));
    return a;
}
__device__ __forceinline__ void cp_async16(uint32_t dst, const void* src) {
    asm volatile("cp.async.cg.shared.global [%0], [%1], 16;" :: "r"(dst), "l"(src));
}
#define CP_COMMIT()  asm volatile("cp.async.commit_group;" ::: "memory")
#define CP_WAIT0()   asm volatile("cp.async.wait_group 0;" ::: "memory")

__device__ __forceinline__ void ldsm_x4(uint32_t a, uint32_t& r0, uint32_t& r1,
                                        uint32_t& r2, uint32_t& r3) {
    asm volatile("ldmatrix.sync.aligned.m8n8.x4.shared.b16 {%0,%1,%2,%3}, [%4];"
                 : "=r"(r0), "=r"(r1), "=r"(r2), "=r"(r3) : "r"(a));
}
__device__ __forceinline__ void ldsm_x2(uint32_t a, uint32_t& r0, uint32_t& r1) {
    asm volatile("ldmatrix.sync.aligned.m8n8.x2.shared.b16 {%0,%1}, [%2];"
                 : "=r"(r0), "=r"(r1) : "r"(a));
}
__device__ __forceinline__ void mma16816(float* d, const uint32_t* a, const uint32_t* b) {
    asm volatile(
        "mma.sync.aligned.m16n8k16.row.col.f32.bf16.bf16.f32 "
        "{%0,%1,%2,%3}, {%4,%5,%6,%7}, {%8,%9}, {%0,%1,%2,%3};"
        : "+f"(d[0]), "+f"(d[1]), "+f"(d[2]), "+f"(d[3])
        : "r"(a[0]), "r"(a[1]), "r"(a[2]), "r"(a[3]), "r"(b[0]), "r"(b[1]));
}

__device__ __forceinline__ void split_bf16(float x, __nv_bfloat16& h, __nv_bfloat16& l) {
    h = __float2bfloat16(x);
    l = __float2bfloat16(x - __bfloat162float(h));
}

// ---------------------------------------------------------------------------
// Kernel 1: build kv directly as (hi, lo) bf16 split, padded to MPAD rows.
// ---------------------------------------------------------------------------
__global__ void __launch_bounds__(256) build_a_bf16_kernel(
    const float* __restrict__ xb, const float* __restrict__ prompt,
    const float* __restrict__ pe)
{
    long i = (long)blockIdx.x * 256 + threadIdx.x;    // float4 index over MPAD*256
    const long total = (long)MPAD * (KD_ / 4);
    if (i >= total) return;
    int  c4 = (int)(i & 255);
    long bt = i >> 8;
    float4 v = make_float4(0.f, 0.f, 0.f, 0.f);
    if (bt < M_KV) {
        int t = (int)(bt % T_);
        int b = (int)(bt / T_);
        if (t == 0) {
            v = reinterpret_cast<const float4*>(prompt)[c4];
        } else {
            float4 x = reinterpret_cast<const float4*>(xb)[((long)b * TB_ + (t - 1)) * 256 + c4];
            float4 p = reinterpret_cast<const float4*>(pe)[(long)(t - 1) * 256 + c4];
            v.x = x.x + p.x; v.y = x.y + p.y; v.z = x.z + p.z; v.w = x.w + p.w;
        }
    }
    __nv_bfloat16 h[4], l[4];
    split_bf16(v.x, h[0], l[0]); split_bf16(v.y, h[1], l[1]);
    split_bf16(v.z, h[2], l[2]); split_bf16(v.w, h[3], l[3]);
    __nv_bfloat162* Hp = reinterpret_cast<__nv_bfloat162*>(g_Ah);
    __nv_bfloat162* Lp = reinterpret_cast<__nv_bfloat162*>(g_Al);
    Hp[i * 2 + 0] = __nv_bfloat162(h[0], h[1]);
    Hp[i * 2 + 1] = __nv_bfloat162(h[2], h[3]);
    Lp[i * 2 + 0] = __nv_bfloat162(l[0], l[1]);
    Lp[i * 2 + 1] = __nv_bfloat162(l[2], l[3]);
}

// ---------------------------------------------------------------------------
// Kernel 2: split Wk / Wv into bf16 (hi, lo)
// ---------------------------------------------------------------------------
__global__ void __launch_bounds__(256) prep_w_kernel(
    const float* __restrict__ Wk, const float* __restrict__ Wv)
{
    long i = (long)blockIdx.x * 256 + threadIdx.x;   // float4 idx over 2 * 1024*256
    const long total = 2L * KD_ * (KD_ / 4);
    if (i >= total) return;
    int  w = (int)(i >> 18);                         // 0: Wk, 1: Wv
    long j = i & 0x3FFFF;
    const float4 v = reinterpret_cast<const float4*>(w ? Wv : Wk)[j];
    __nv_bfloat16 h[4], l[4];
    split_bf16(v.x, h[0], l[0]); split_bf16(v.y, h[1], l[1]);
    split_bf16(v.z, h[2], l[2]); split_bf16(v.w, h[3], l[3]);
    __nv_bfloat162* Hp = reinterpret_cast<__nv_bfloat162*>(g_Wh);
    __nv_bfloat162* Lp = reinterpret_cast<__nv_bfloat162*>(g_Wl);
    Hp[i * 2 + 0] = __nv_bfloat162(h[0], h[1]);
    Hp[i * 2 + 1] = __nv_bfloat162(h[2], h[3]);
    Lp[i * 2 + 0] = __nv_bfloat162(l[0], l[1]);
    Lp[i * 2 + 1] = __nv_bfloat162(l[2], l[3]);
}

// ---------------------------------------------------------------------------
// Kernel 3: mma.sync bf16x3 NT GEMM.  C[m,n] = sum_k A[m,k] * W[n,k]
// grid (65 m-tiles, 8 n-tiles, 2 weights), 256 threads = 8 warps (2m x 4n).
// Warp tile 64x32. K-chunks of 64, single-buffered cp.async.
// D = Ah*Bh + Ah*Bl + Al*Bh accumulated in fp32 (residual ~2^-16).
// ---------------------------------------------------------------------------
namespace {
constexpr int LDT    = 72;              // bf16 elems per smem row (conflict-free)
constexpr int TILE_E = 128 * LDT;       // elems per tile
constexpr int GSM_TOTAL = 4 * TILE_E * 2;  // 73728 B
constexpr int BKC = 64;
constexpr int N_CHUNKS = KD_ / BKC;     // 16
}

__global__ void __launch_bounds__(256, 2) gemm_mma_kernel()
{
    extern __shared__ __nv_bfloat16 smem_t[];
    __nv_bfloat16* sAh = smem_t;
    __nv_bfloat16* sAl = smem_t + TILE_E;
    __nv_bfloat16* sBh = smem_t + 2 * TILE_E;
    __nv_bfloat16* sBl = smem_t + 3 * TILE_E;

    const int tid  = threadIdx.x;
    const int lane = tid & 31;
    const int wid  = tid >> 5;
    const int wm   = wid >> 2;          // 0..1
    const int wn   = wid & 3;           // 0..3
    const int m0   = blockIdx.x * 128;
    const int n0   = blockIdx.y * 128;
    const int w    = blockIdx.z;

    const __nv_bfloat16* gAh = g_Ah + (long)m0 * KD_;
    const __nv_bfloat16* gAl = g_Al + (long)m0 * KD_;
    const __nv_bfloat16* gBh = g_Wh + ((long)w << 20) + (long)n0 * KD_;
    const __nv_bfloat16* gBl = g_Wl + ((long)w << 20) + (long)n0 * KD_;

    // ldmatrix per-thread base addresses (byte)
    const uint32_t aoff = ((wm * 64 + (lane & 15)) * LDT + (lane >> 4) * 8) * 2;
    const uint32_t boff = ((wn * 32 + (lane & 7)) * LDT + ((lane >> 3) & 1) * 8) * 2;
    const uint32_t sAh_b = smem_u32(sAh), sAl_b = smem_u32(sAl);
    const uint32_t sBh_b = smem_u32(sBh), sBl_b = smem_u32(sBl);

    float acc[4][4][4];
#pragma unroll
    for (int i = 0; i < 4; i++)
#pragma unroll
        for (int j = 0; j < 4; j++)
#pragma unroll
            for (int q = 0; q < 4; q++) acc[i][j][q] = 0.f;

    for (int c = 0; c < N_CHUNKS; c++) {
        // ---- fill 4 tiles (128 x 64 bf16 each) via cp.async ----
        const __nv_bfloat16* srcs[4] = {gAh, gAl, gBh, gBl};
        const uint32_t dsts[4] = {sAh_b, sAl_b, sBh_b, sBl_b};
#pragma unroll
        for (int tl = 0; tl < 4; tl++) {
#pragma unroll
            for (int it = 0; it < 4; it++) {
                const int idx = it * 256 + tid;        // 0..1023
                const int row = idx >> 3, seg = idx & 7;
                const void* gp = srcs[tl] + (long)row * KD_ + c * BKC + seg * 8;
                cp_async16(dsts[tl] + row * (LDT * 2) + seg * 16, gp);
            }
        }
        CP_COMMIT();
        CP_WAIT0();
        __syncthreads();

        // ---- compute: 4 k16 steps ----
#pragma unroll
        for (int ks = 0; ks < 4; ks++) {
            const uint32_t kb = ks * 32;   // byte offset of k16 step
            // B fragments for all 4 nt (hi + lo)
            uint32_t bh[4][2], bl[4][2];
#pragma unroll
            for (int nt = 0; nt < 4; nt++) {
                const uint32_t bo = boff + nt * (8 * LDT * 2) + kb;
                ldsm_x2(sBh_b + bo, bh[nt][0], bh[nt][1]);
                ldsm_x2(sBl_b + bo, bl[nt][0], bl[nt][1]);
            }
#pragma unroll
            for (int mt = 0; mt < 4; mt++) {
                const uint32_t ao = aoff + mt * (16 * LDT * 2) + kb;
                uint32_t ah[4], al[4];
                ldsm_x4(sAh_b + ao, ah[0], ah[1], ah[2], ah[3]);
                ldsm_x4(sAl_b + ao, al[0], al[1], al[2], al[3]);
#pragma unroll
                for (int nt = 0; nt < 4; nt++) {
                    mma16816(acc[mt][nt], ah, bh[nt]);
                    mma16816(acc[mt][nt], ah, bl[nt]);
                    mma16816(acc[mt][nt], al, bh[nt]);
                }
            }
        }
        __syncthreads();
    }

    // ---- epilogue: fragment -> global fp32 ----
    float* C = w ? g_V : g_K;
    const int r0 = lane >> 2;          // 0..7
    const int cc = (lane & 3) * 2;     // 0,2,4,6
#pragma unroll
    for (int mt = 0; mt < 4; mt++) {
#pragma unroll
        for (int nt = 0; nt < 4; nt++) {
            const int mA = m0 + wm * 64 + mt * 16 + r0;
            const int nn = n0 + wn * 32 + nt * 8 + cc;
            if (mA < M_KV) {
                *reinterpret_cast<float2*>(&C[(long)mA * E_ + nn]) =
                    make_float2(acc[mt][nt][0], acc[mt][nt][1]);
            }
            if (mA + 8 < M_KV) {
                *reinterpret_cast<float2*>(&C[(long)(mA + 8) * E_ + nn]) =
                    make_float2(acc[mt][nt][2], acc[mt][nt][3]);
            }
        }
    }
}

// ---------------------------------------------------------------------------
// Kernel 4: tiny pos GEMM (k-split) + reduce (unchanged; ~12us)
// ---------------------------------------------------------------------------
__global__ void __launch_bounds__(256) gemm_pos_kernel(
    const float* __restrict__ pe, const float* __restrict__ Wpos)
{
    constexpr int BK = 16, KS = KD_ / KSPLIT_;
    __shared__ float As[BK][64 + 4];
    __shared__ float Ws[BK][64 + 4];
    const int tid  = threadIdx.x;
    const int tx   = tid & 15, ty = tid >> 4;
    const int lrow = tid >> 2, lseg = tid & 3;
    const int n0   = blockIdx.x * 64;
    const int k0   = blockIdx.y * KS;

    float acc[4][4] = {};
    for (int c0 = k0; c0 < k0 + KS; c0 += BK) {
        const int cc = c0 + lseg * 4;
        float4 a = make_float4(0.f, 0.f, 0.f, 0.f);
        if (lrow < NPE_) a = *reinterpret_cast<const float4*>(&pe[(long)lrow * KD_ + cc]);
        float4 w = *reinterpret_cast<const float4*>(&Wpos[(long)(n0 + lrow) * KD_ + cc]);
        __syncthreads();
        As[lseg*4+0][lrow] = a.x; As[lseg*4+1][lrow] = a.y;
        As[lseg*4+2][lrow] = a.z; As[lseg*4+3][lrow] = a.w;
        Ws[lseg*4+0][lrow] = w.x; Ws[lseg*4+1][lrow] = w.y;
        Ws[lseg*4+2][lrow] = w.z; Ws[lseg*4+3][lrow] = w.w;
        __syncthreads();
#pragma unroll
        for (int kk = 0; kk < BK; kk++) {
            float4 a4 = *reinterpret_cast<const float4*>(&As[kk][ty * 4]);
            float4 w4 = *reinterpret_cast<const float4*>(&Ws[kk][tx * 4]);
            acc[0][0] += a4.x*w4.x; acc[0][1] += a4.x*w4.y; acc[0][2] += a4.x*w4.z; acc[0][3] += a4.x*w4.w;
            acc[1][0] += a4.y*w4.x; acc[1][1] += a4.y*w4.y; acc[1][2] += a4.y*w4.z; acc[1][3] += a4.y*w4.w;
            acc[2][0] += a4.z*w4.x; acc[2][1] += a4.z*w4.y; acc[2][2] += a4.z*w4.z; acc[2][3] += a4.z*w4.w;
            acc[3][0] += a4.w*w4.x; acc[3][1] += a4.w*w4.y; acc[3][2] += a4.w*w4.z; acc[3][3] += a4.w*w4.w;
        }
    }
#pragma unroll
    for (int ii = 0; ii < 4; ii++) {
        int m = ty * 4 + ii;
        if (m < NPE_) {
            *reinterpret_cast<float4*>(
                &g_p50p[((long)blockIdx.y * NPE_ + m) * E_ + n0 + tx * 4]) =
                make_float4(acc[ii][0], acc[ii][1], acc[ii][2], acc[ii][3]);
        }
    }
}

__global__ void __launch_bounds__(256) reduce_pos_kernel() {
    int i = blockIdx.x * 256 + threadIdx.x;
    const int total = NPE_ * (E_ / 4);
    if (i >= total) return;
    float4 s = make_float4(0.f, 0.f, 0.f, 0.f);
#pragma unroll
    for (int ks = 0; ks < KSPLIT_; ks++) {
        float4 v = reinterpret_cast<const float4*>(g_p50p)[(long)ks * total + i];
        s.x += v.x; s.y += v.y; s.z += v.z; s.w += v.w;
    }
    reinterpret_cast<float4*>(g_p50)[i] = s;
}

// ---------------------------------------------------------------------------
// Kernel 5: flash attention (fp32 + f32x2 packing) — unchanged from R2
// ---------------------------------------------------------------------------
namespace {
constexpr int PADQ = 65;
constexpr int PADV = 33;
constexpr int PADP = 68;
constexpr int SMEM_FLASH = (2 * 32 * PADQ + 64 * PADV) * 8 + 64 * PADP * 4;
}

__global__ void __launch_bounds__(256) flash_kernel(
    const float* __restrict__ dbg, const float* __restrict__ gates,
    float* __restrict__ out)
{
    extern __shared__ char smraw[];
    f32x2* Qp  = reinterpret_cast<f32x2*>(smraw);
    f32x2* Kp  = Qp + 32 * PADQ;
    f32x2* Vpj = Kp + 32 * PADQ;
    float* Ps  = reinterpret_cast<float*>(Vpj + 64 * PADV);

    const int tid  = threadIdx.x;
    const int tx   = tid & 15, ty = tid >> 4;
    const int lrow = tid >> 2, lseg = tid & 3;
    const int q0 = blockIdx.x * 64;
    const int h  = blockIdx.y;
    const int b  = blockIdx.z;
    const float QSC = 0.125f * 1.4426950408889634f;

    {
        const int p = q0 + lrow;
        if (p < QL_) {
            const int pidx = (p * NPE_) / QL_;
            const float* dq = &dbg[(((long)(b * H_ + h) * QL_) + p) * HD_];
            const float* pp = &g_p50[(long)pidx * E_ + h * HD_];
#pragma unroll
            for (int w = 0; w < 4; w++) {
                const int d0 = (lseg + 4 * w) * 4;
                float4 dv = *reinterpret_cast<const float4*>(&dq[d0]);
                float4 pv = *reinterpret_cast<const float4*>(&pp[d0]);
                Qp[(d0 >> 1) * PADQ + lrow]       = pk2((dv.x + pv.x) * QSC, (dv.y + pv.y) * QSC);
                Qp[((d0 >> 1) + 1) * PADQ + lrow] = pk2((dv.z + pv.z) * QSC, (dv.w + pv.w) * QSC);
            }
        } else {
#pragma unroll
            for (int w = 0; w < 4; w++) {
                const int d0 = (lseg + 4 * w) * 4;
                Qp[(d0 >> 1) * PADQ + lrow]       = 0ull;
                Qp[((d0 >> 1) + 1) * PADQ + lrow] = 0ull;
            }
        }
    }

    float mst[4], lst[4];
#pragma unroll
    for (int ii = 0; ii < 4; ii++) { mst[ii] = -1e30f; lst[ii] = 0.f; }
    f32x2 acc2[4][4];
#pragma unroll
    for (int ii = 0; ii < 4; ii++)
#pragma unroll
        for (int jj = 0; jj < 4; jj++) acc2[ii][jj] = 0ull;

    for (int t0 = 0; t0 < T_; t0 += 64) {
        const int vk = (T_ - t0 < 64) ? (T_ - t0) : 64;
        {
            const int j = lrow;
            float* Vf = reinterpret_cast<float*>(Vpj);
            if (j < vk) {
                const float* kr = &g_K[((long)b * T_ + t0 + j) * E_ + h * HD_];
                const float* vr = &g_V[((long)b * T_ + t0 + j) * E_ + h * HD_];
                const int vo = 2 * (j >> 1) + (j & 1);
#pragma unroll
                for (int w = 0; w < 4; w++) {
                    const int d0 = (lseg + 4 * w) * 4;
                    float4 kv4 = *reinterpret_cast<const float4*>(&kr[d0]);
                    Kp[(d0 >> 1) * PADQ + j]       = pk2(kv4.x, kv4.y);
                    Kp[((d0 >> 1) + 1) * PADQ + j] = pk2(kv4.z, kv4.w);
                    float4 vv4 = *reinterpret_cast<const float4*>(&vr[d0]);
                    Vf[(d0 + 0) * 2 * PADV + vo] = vv4.x;
                    Vf[(d0 + 1) * 2 * PADV + vo] = vv4.y;
                    Vf[(d0 + 2) * 2 * PADV + vo] = vv4.z;
                    Vf[(d0 + 3) * 2 * PADV + vo] = vv4.w;
                }
            } else {
                const int vo = 2 * (j >> 1) + (j & 1);
#pragma unroll
                for (int w = 0; w < 4; w++) {
                    const int d0 = (lseg + 4 * w) * 4;
                    Kp[(d0 >> 1) * PADQ + j]       = 0ull;
                    Kp[((d0 >> 1) + 1) * PADQ + j] = 0ull;
                    Vf[(d0 + 0) * 2 * PADV + vo] = 0.f;
                    Vf[(d0 + 1) * 2 * PADV + vo] = 0.f;
                    Vf[(d0 + 2) * 2 * PADV + vo] = 0.f;
                    Vf[(d0 + 3) * 2 * PADV + vo] = 0.f;
                }
            }
        }
        __syncthreads();

        f32x2 s2[4][4];
#pragma unroll
        for (int ii = 0; ii < 4; ii++)
#pragma unroll
            for (int jj = 0; jj < 4; jj++) s2[ii][jj] = 0ull;
#pragma unroll 4
        for (int d2 = 0; d2 < 32; d2++) {
            f32x2 qv[4], kv[4];
#pragma unroll
            for (int ii = 0; ii < 4; ii++) qv[ii] = Qp[d2 * PADQ + ty + 16 * ii];
#pragma unroll
            for (int jj = 0; jj < 4; jj++) kv[jj] = Kp[d2 * PADQ + tx + 16 * jj];
#pragma unroll
            for (int ii = 0; ii < 4; ii++)
#pragma unroll
                for (int jj = 0; jj < 4; jj++) ffma2(s2[ii][jj], qv[ii], kv[jj]);
        }

        float s[4][4];
#pragma unroll
        for (int ii = 0; ii < 4; ii++)
#pragma unroll
            for (int jj = 0; jj < 4; jj++) {
                float2 u = upk(s2[ii][jj]);
                s[ii][jj] = u.x + u.y;
            }

#pragma unroll
        for (int ii = 0; ii < 4; ii++) {
            const int r = ty + 16 * ii;
            float mx = -1e30f;
#pragma unroll
            for (int jj = 0; jj < 4; jj++)
                if (tx + 16 * jj < vk) mx = fmaxf(mx, s[ii][jj]);
            mx = fmaxf(mx, __shfl_xor_sync(0xffffffffu, mx, 1));
            mx = fmaxf(mx, __shfl_xor_sync(0xffffffffu, mx, 2));
            mx = fmaxf(mx, __shfl_xor_sync(0xffffffffu, mx, 4));
            mx = fmaxf(mx, __shfl_xor_sync(0xffffffffu, mx, 8));
            const float m_new = fmaxf(mst[ii], mx);
            const float corr = exp2f(mst[ii] - m_new);
            float sum = 0.f;
            float p[4];
#pragma unroll
            for (int jj = 0; jj < 4; jj++) {
                p[jj] = (tx + 16 * jj < vk) ? exp2f(s[ii][jj] - m_new) : 0.f;
                sum += p[jj];
            }
            sum += __shfl_xor_sync(0xffffffffu, sum, 1);
            sum += __shfl_xor_sync(0xffffffffu, sum, 2);
            sum += __shfl_xor_sync(0xffffffffu, sum, 4);
            sum += __shfl_xor_sync(0xffffffffu, sum, 8);
            lst[ii] = lst[ii] * corr + sum;
            mst[ii] = m_new;
            const f32x2 c2 = pk2(corr, corr);
#pragma unroll
            for (int jj = 0; jj < 4; jj++) acc2[ii][jj] = mul2(acc2[ii][jj], c2);
#pragma unroll
            for (int jj = 0; jj < 4; jj++) Ps[r * PADP + tx + 16 * jj] = p[jj];
        }
        __syncthreads();

#pragma unroll 4
        for (int j2 = 0; j2 < 32; j2++) {
            f32x2 pv[4], vv[4];
#pragma unroll
            for (int ii = 0; ii < 4; ii++)
                pv[ii] = *reinterpret_cast<const f32x2*>(&Ps[(ty + 16 * ii) * PADP + 2 * j2]);
#pragma unroll
            for (int jj = 0; jj < 4; jj++) vv[jj] = Vpj[(tx + 16 * jj) * PADV + j2];
#pragma unroll
            for (int ii = 0; ii < 4; ii++)
#pragma unroll
                for (int jj = 0; jj < 4; jj++) ffma2(acc2[ii][jj], pv[ii], vv[jj]);
        }
        __syncthreads();
    }

    const float g = gates[0];
#pragma unroll
    for (int ii = 0; ii < 4; ii++) {
        const int p = q0 + ty + 16 * ii;
        if (p < QL_) {
            const float inv = g / lst[ii];
            float* orow = &out[((long)b * QL_ + p) * E_ + h * HD_];
#pragma unroll
            for (int jj = 0; jj < 4; jj++) {
                float2 u = upk(acc2[ii][jj]);
                orow[tx + 16 * jj] = (u.x + u.y) * inv;
            }
        }
    }
}

// ---------------------------------------------------------------------------
// Launch
// ---------------------------------------------------------------------------
extern "C" void kernel_launch(void* const* d_in, const int* in_sizes, int n_in,
                              void* d_out, int out_size)
{
    const float* x_b    = (const float*)d_in[1];
    const float* dbg    = (const float*)d_in[2];
    const float* Wk     = (const float*)d_in[3];
    const float* Wv     = (const float*)d_in[4];
    const float* Wpos   = (const float*)d_in[5];
    const float* prompt = (const float*)d_in[6];
    const float* gates  = (const float*)d_in[7];
    const float* pe     = (const float*)d_in[8];
    float* out = (float*)d_out;

    // 1) build bf16-split A (kv) and W
    {
        const long total4 = (long)MPAD * (KD_ / 4);
        build_a_bf16_kernel<<<(int)((total4 + 255) / 256), 256>>>(x_b, prompt, pe);
        const long wtotal4 = 2L * KD_ * (KD_ / 4);
        prep_w_kernel<<<(int)((wtotal4 + 255) / 256), 256>>>(Wk, Wv);
    }
    // 2) tensor-core (mma.sync) K/V projections (bf16x3)
    {
        cudaFuncSetAttribute(gemm_mma_kernel, cudaFuncAttributeMaxDynamicSharedMemorySize, GSM_TOTAL);
        dim3 g(MPAD / 128, E_ / 128, 2);
        gemm_mma_kernel<<<g, 256, GSM_TOTAL>>>();
    }
    // 3) tiny pos GEMM
    {
        dim3 g(E_ / 64, KSPLIT_);
        gemm_pos_kernel<<<g, 256>>>(pe, Wpos);
        const int total4 = NPE_ * (E_ / 4);
        reduce_pos_kernel<<<(total4 + 255) / 256, 256>>>();
    }
    // 4) flash attention
    {
        cudaFuncSetAttribute(flash_kernel, cudaFuncAttributeMaxDynamicSharedMemorySize, SMEM_FLASH);
        dim3 g((QL_ + 63) / 64, H_, B_);
        flash_kernel<<<g, 256, SMEM_FLASH>>>(dbg, gates, out);
    }
}

// round 5
// speedup vs baseline: 2.5509x; 1.8051x over previous
#include <cuda_runtime.h>
#include <cuda_bf16.h>
#include <math.h>
#include <stdint.h>

// ---------------------------------------------------------------------------
// Problem constants (B=4, T_B=2048, Q_LEN=801)
// ---------------------------------------------------------------------------
namespace {
constexpr int B_   = 4;
constexpr int H_   = 16;
constexpr int HD_  = 64;
constexpr int E_   = 1024;
constexpr int QL_  = 801;
constexpr int TB_  = 2048;
constexpr int T_   = 2049;
constexpr int KD_  = 1024;
constexpr int NPE_ = 50;
constexpr int KSPLIT_ = 8;
constexpr int M_KV  = B_ * T_;           // 8196
constexpr int MPAD  = 8320;              // 65 * 128
}

// ---------------------------------------------------------------------------
// Device scratch
// ---------------------------------------------------------------------------
__device__ float g_K  [(size_t)B_ * T_ * E_];
__device__ float g_V  [(size_t)B_ * T_ * E_];
__device__ float g_p50[(size_t)NPE_ * E_];
__device__ float g_p50p[(size_t)KSPLIT_ * NPE_ * E_];
__device__ __nv_bfloat16 g_Ah[(size_t)MPAD * KD_];
__device__ __nv_bfloat16 g_Al[(size_t)MPAD * KD_];
__device__ __nv_bfloat16 g_Wh[(size_t)2 * KD_ * KD_];
__device__ __nv_bfloat16 g_Wl[(size_t)2 * KD_ * KD_];

// ---------------------------------------------------------------------------
// Helpers (family-portable: cp.async, ldmatrix, mma.sync)
// ---------------------------------------------------------------------------
__device__ __forceinline__ uint32_t smem_u32(const void* p) {
    uint32_t a;
    asm("{ .reg .u64 t; cvta.to.shared.u64 t, %1; cvt.u32.u64 %0, t; }" : "=r"(a) : "l"(p));
    return a;
}
__device__ __forceinline__ void cp_async16(uint32_t dst, const void* src) {
    asm volatile("cp.async.cg.shared.global [%0], [%1], 16;" :: "r"(dst), "l"(src));
}
#define CP_COMMIT()  asm volatile("cp.async.commit_group;" ::: "memory")
#define CP_WAIT0()   asm volatile("cp.async.wait_group 0;" ::: "memory")
#define CP_WAIT1()   asm volatile("cp.async.wait_group 1;" ::: "memory")

__device__ __forceinline__ void ldsm_x4(uint32_t a, uint32_t& r0, uint32_t& r1,
                                        uint32_t& r2, uint32_t& r3) {
    asm volatile("ldmatrix.sync.aligned.m8n8.x4.shared.b16 {%0,%1,%2,%3}, [%4];"
                 : "=r"(r0), "=r"(r1), "=r"(r2), "=r"(r3) : "r"(a));
}
__device__ __forceinline__ void mma16816(float* d, const uint32_t* a, const uint32_t* b) {
    asm volatile(
        "mma.sync.aligned.m16n8k16.row.col.f32.bf16.bf16.f32 "
        "{%0,%1,%2,%3}, {%4,%5,%6,%7}, {%8,%9}, {%0,%1,%2,%3};"
        : "+f"(d[0]), "+f"(d[1]), "+f"(d[2]), "+f"(d[3])
        : "r"(a[0]), "r"(a[1]), "r"(a[2]), "r"(a[3]), "r"(b[0]), "r"(b[1]));
}
__device__ __forceinline__ void split_bf16(float x, __nv_bfloat16& h, __nv_bfloat16& l) {
    h = __float2bfloat16(x);
    l = __float2bfloat16(x - __bfloat162float(h));
}
// pack two fp32 -> bf16x2 (hi split) + residual bf16x2 (lo split)
__device__ __forceinline__ void split_pack(float p0, float p1, uint32_t& hp, uint32_t& lp) {
    __nv_bfloat162 hv = __floats2bfloat162_rn(p0, p1);   // .x = p0 (low half)
    hp = *reinterpret_cast<uint32_t*>(&hv);
    float h0 = __bfloat162float(hv.x);
    float h1 = __bfloat162float(hv.y);
    __nv_bfloat162 lv = __floats2bfloat162_rn(p0 - h0, p1 - h1);
    lp = *reinterpret_cast<uint32_t*>(&lv);
}

// ---------------------------------------------------------------------------
// Kernel 1: build kv as (hi, lo) bf16 split, padded to MPAD rows.
// ---------------------------------------------------------------------------
__global__ void __launch_bounds__(256) build_a_bf16_kernel(
    const float* __restrict__ xb, const float* __restrict__ prompt,
    const float* __restrict__ pe)
{
    long i = (long)blockIdx.x * 256 + threadIdx.x;    // float4 index over MPAD*256
    const long total = (long)MPAD * (KD_ / 4);
    if (i >= total) return;
    int  c4 = (int)(i & 255);
    long bt = i >> 8;
    float4 v = make_float4(0.f, 0.f, 0.f, 0.f);
    if (bt < M_KV) {
        int t = (int)(bt % T_);
        int b = (int)(bt / T_);
        if (t == 0) {
            v = reinterpret_cast<const float4*>(prompt)[c4];
        } else {
            float4 x = reinterpret_cast<const float4*>(xb)[((long)b * TB_ + (t - 1)) * 256 + c4];
            float4 p = reinterpret_cast<const float4*>(pe)[(long)(t - 1) * 256 + c4];
            v.x = x.x + p.x; v.y = x.y + p.y; v.z = x.z + p.z; v.w = x.w + p.w;
        }
    }
    __nv_bfloat16 h[4], l[4];
    split_bf16(v.x, h[0], l[0]); split_bf16(v.y, h[1], l[1]);
    split_bf16(v.z, h[2], l[2]); split_bf16(v.w, h[3], l[3]);
    __nv_bfloat162* Hp = reinterpret_cast<__nv_bfloat162*>(g_Ah);
    __nv_bfloat162* Lp = reinterpret_cast<__nv_bfloat162*>(g_Al);
    Hp[i * 2 + 0] = __nv_bfloat162(h[0], h[1]);
    Hp[i * 2 + 1] = __nv_bfloat162(h[2], h[3]);
    Lp[i * 2 + 0] = __nv_bfloat162(l[0], l[1]);
    Lp[i * 2 + 1] = __nv_bfloat162(l[2], l[3]);
}

// ---------------------------------------------------------------------------
// Kernel 2: split Wk / Wv into bf16 (hi, lo)
// ---------------------------------------------------------------------------
__global__ void __launch_bounds__(256) prep_w_kernel(
    const float* __restrict__ Wk, const float* __restrict__ Wv)
{
    long i = (long)blockIdx.x * 256 + threadIdx.x;   // float4 idx over 2 * 1024*256
    const long total = 2L * KD_ * (KD_ / 4);
    if (i >= total) return;
    int  w = (int)(i >> 18);                         // 0: Wk, 1: Wv
    long j = i & 0x3FFFF;
    const float4 v = reinterpret_cast<const float4*>(w ? Wv : Wk)[j];
    __nv_bfloat16 h[4], l[4];
    split_bf16(v.x, h[0], l[0]); split_bf16(v.y, h[1], l[1]);
    split_bf16(v.z, h[2], l[2]); split_bf16(v.w, h[3], l[3]);
    __nv_bfloat162* Hp = reinterpret_cast<__nv_bfloat162*>(g_Wh);
    __nv_bfloat162* Lp = reinterpret_cast<__nv_bfloat162*>(g_Wl);
    Hp[i * 2 + 0] = __nv_bfloat162(h[0], h[1]);
    Hp[i * 2 + 1] = __nv_bfloat162(h[2], h[3]);
    Lp[i * 2 + 0] = __nv_bfloat162(l[0], l[1]);
    Lp[i * 2 + 1] = __nv_bfloat162(l[2], l[3]);
}

// ---------------------------------------------------------------------------
// Kernel 3: mma.sync bf16x3 NT GEMM with 2-stage cp.async pipeline.
// C[m,n] = sum_k A[m,k] * W[n,k].  grid (65, 8, 2), 256 threads = 8 warps (2m x 4n).
// K-chunks of 32, double-buffered.
// ---------------------------------------------------------------------------
namespace {
constexpr int LDT2   = 40;                 // bf16 elems per smem row (32 + 8 pad)
constexpr int PTILE  = 128 * LDT2;         // 5120 elems per tile
constexpr int PSTAGE = 4 * PTILE;          // 20480 elems per stage
constexpr int GSM2_TOTAL = 2 * PSTAGE * 2; // 81920 B
constexpr int BKC2 = 32;
constexpr int NCH2 = KD_ / BKC2;           // 32
}

__global__ void __launch_bounds__(256, 2) gemm_mma_kernel()
{
    extern __shared__ __nv_bfloat16 ps[];
    const uint32_t smb = smem_u32(ps);

    const int tid  = threadIdx.x;
    const int lane = tid & 31;
    const int wid  = tid >> 5;
    const int wm   = wid >> 2;          // 0..1
    const int wn   = wid & 3;           // 0..3
    const int m0   = blockIdx.x * 128;
    const int n0   = blockIdx.y * 128;
    const int w    = blockIdx.z;

    const __nv_bfloat16* srcs[4] = {
        g_Ah + (long)m0 * KD_,
        g_Al + (long)m0 * KD_,
        g_Wh + ((long)w << 20) + (long)n0 * KD_,
        g_Wl + ((long)w << 20) + (long)n0 * KD_ };

    // per-thread cp.async mapping: 2 ops per tile (512 rows-of-8 / 256 thr)
    const int cprow0 = tid >> 2, cpseg0 = tid & 3;                 // idx = tid
    const int cprow1 = (256 + tid) >> 2, cpseg1 = (256 + tid) & 3; // idx = 256+tid

    // ldmatrix addresses
    const uint32_t aoff  = ((wm * 64 + (lane & 15)) * LDT2 + (lane >> 4) * 8) * 2;
    const uint32_t b4off = ((lane & 7) * LDT2 + ((lane >> 3) & 1) * 8 +
                           ((lane >> 4) & 1) * 8 * LDT2) * 2 + wn * (32 * LDT2 * 2);

    float acc[4][4][4];
#pragma unroll
    for (int i = 0; i < 4; i++)
#pragma unroll
        for (int j = 0; j < 4; j++)
#pragma unroll
            for (int q = 0; q < 4; q++) acc[i][j][q] = 0.f;

    auto issue = [&](int c, int s) {
        const uint32_t sb = smb + (uint32_t)(s * PSTAGE) * 2;
#pragma unroll
        for (int tl = 0; tl < 4; tl++) {
            const uint32_t tb = sb + (uint32_t)(tl * PTILE) * 2;
            cp_async16(tb + cprow0 * (LDT2 * 2) + cpseg0 * 16,
                       srcs[tl] + (long)cprow0 * KD_ + c * BKC2 + cpseg0 * 8);
            cp_async16(tb + cprow1 * (LDT2 * 2) + cpseg1 * 16,
                       srcs[tl] + (long)cprow1 * KD_ + c * BKC2 + cpseg1 * 8);
        }
    };

    issue(0, 0);
    CP_COMMIT();

    for (int c = 0; c < NCH2; c++) {
        const int s = c & 1;
        const bool more = (c + 1 < NCH2);
        if (more) { issue(c + 1, (c + 1) & 1); CP_COMMIT(); }
        if (more) { CP_WAIT1(); } else { CP_WAIT0(); }
        __syncthreads();

        const uint32_t sA_h = smb + (uint32_t)(s * PSTAGE + 0 * PTILE) * 2;
        const uint32_t sA_l = smb + (uint32_t)(s * PSTAGE + 1 * PTILE) * 2;
        const uint32_t sB_h = smb + (uint32_t)(s * PSTAGE + 2 * PTILE) * 2;
        const uint32_t sB_l = smb + (uint32_t)(s * PSTAGE + 3 * PTILE) * 2;

#pragma unroll
        for (int ks = 0; ks < 2; ks++) {
            const uint32_t kb = ks * 32;
            uint32_t bh[2][4], bl[2][4];
#pragma unroll
            for (int nt2 = 0; nt2 < 2; nt2++) {
                const uint32_t bo = b4off + nt2 * (16 * LDT2 * 2) + kb;
                ldsm_x4(sB_h + bo, bh[nt2][0], bh[nt2][1], bh[nt2][2], bh[nt2][3]);
                ldsm_x4(sB_l + bo, bl[nt2][0], bl[nt2][1], bl[nt2][2], bl[nt2][3]);
            }
#pragma unroll
            for (int mt = 0; mt < 4; mt++) {
                const uint32_t ao = aoff + mt * (16 * LDT2 * 2) + kb;
                uint32_t ah[4], al[4];
                ldsm_x4(sA_h + ao, ah[0], ah[1], ah[2], ah[3]);
                ldsm_x4(sA_l + ao, al[0], al[1], al[2], al[3]);
#pragma unroll
                for (int nt2 = 0; nt2 < 2; nt2++) {
                    mma16816(acc[mt][2*nt2],   ah, bh[nt2]);
                    mma16816(acc[mt][2*nt2],   ah, bl[nt2]);
                    mma16816(acc[mt][2*nt2],   al, bh[nt2]);
                    mma16816(acc[mt][2*nt2+1], ah, bh[nt2] + 2);
                    mma16816(acc[mt][2*nt2+1], ah, bl[nt2] + 2);
                    mma16816(acc[mt][2*nt2+1], al, bh[nt2] + 2);
                }
            }
        }
        __syncthreads();
    }

    // epilogue
    float* C = w ? g_V : g_K;
    const int r0 = lane >> 2;
    const int cc = (lane & 3) * 2;
#pragma unroll
    for (int mt = 0; mt < 4; mt++) {
#pragma unroll
        for (int nt = 0; nt < 4; nt++) {
            const int mA = m0 + wm * 64 + mt * 16 + r0;
            const int nn = n0 + wn * 32 + nt * 8 + cc;
            if (mA < M_KV) {
                *reinterpret_cast<float2*>(&C[(long)mA * E_ + nn]) =
                    make_float2(acc[mt][nt][0], acc[mt][nt][1]);
            }
            if (mA + 8 < M_KV) {
                *reinterpret_cast<float2*>(&C[(long)(mA + 8) * E_ + nn]) =
                    make_float2(acc[mt][nt][2], acc[mt][nt][3]);
            }
        }
    }
}

// ---------------------------------------------------------------------------
// Kernel 4: tiny pos GEMM (k-split) + reduce (~12us, unchanged)
// ---------------------------------------------------------------------------
__global__ void __launch_bounds__(256) gemm_pos_kernel(
    const float* __restrict__ pe, const float* __restrict__ Wpos)
{
    constexpr int BK = 16, KS = KD_ / KSPLIT_;
    __shared__ float As[BK][64 + 4];
    __shared__ float Ws[BK][64 + 4];
    const int tid  = threadIdx.x;
    const int tx   = tid & 15, ty = tid >> 4;
    const int lrow = tid >> 2, lseg = tid & 3;
    const int n0   = blockIdx.x * 64;
    const int k0   = blockIdx.y * KS;

    float acc[4][4] = {};
    for (int c0 = k0; c0 < k0 + KS; c0 += BK) {
        const int cc = c0 + lseg * 4;
        float4 a = make_float4(0.f, 0.f, 0.f, 0.f);
        if (lrow < NPE_) a = *reinterpret_cast<const float4*>(&pe[(long)lrow * KD_ + cc]);
        float4 w = *reinterpret_cast<const float4*>(&Wpos[(long)(n0 + lrow) * KD_ + cc]);
        __syncthreads();
        As[lseg*4+0][lrow] = a.x; As[lseg*4+1][lrow] = a.y;
        As[lseg*4+2][lrow] = a.z; As[lseg*4+3][lrow] = a.w;
        Ws[lseg*4+0][lrow] = w.x; Ws[lseg*4+1][lrow] = w.y;
        Ws[lseg*4+2][lrow] = w.z; Ws[lseg*4+3][lrow] = w.w;
        __syncthreads();
#pragma unroll
        for (int kk = 0; kk < BK; kk++) {
            float4 a4 = *reinterpret_cast<const float4*>(&As[kk][ty * 4]);
            float4 w4 = *reinterpret_cast<const float4*>(&Ws[kk][tx * 4]);
            acc[0][0] += a4.x*w4.x; acc[0][1] += a4.x*w4.y; acc[0][2] += a4.x*w4.z; acc[0][3] += a4.x*w4.w;
            acc[1][0] += a4.y*w4.x; acc[1][1] += a4.y*w4.y; acc[1][2] += a4.y*w4.z; acc[1][3] += a4.y*w4.w;
            acc[2][0] += a4.z*w4.x; acc[2][1] += a4.z*w4.y; acc[2][2] += a4.z*w4.z; acc[2][3] += a4.z*w4.w;
            acc[3][0] += a4.w*w4.x; acc[3][1] += a4.w*w4.y; acc[3][2] += a4.w*w4.z; acc[3][3] += a4.w*w4.w;
        }
    }
#pragma unroll
    for (int ii = 0; ii < 4; ii++) {
        int m = ty * 4 + ii;
        if (m < NPE_) {
            *reinterpret_cast<float4*>(
                &g_p50p[((long)blockIdx.y * NPE_ + m) * E_ + n0 + tx * 4]) =
                make_float4(acc[ii][0], acc[ii][1], acc[ii][2], acc[ii][3]);
        }
    }
}

__global__ void __launch_bounds__(256) reduce_pos_kernel() {
    int i = blockIdx.x * 256 + threadIdx.x;
    const int total = NPE_ * (E_ / 4);
    if (i >= total) return;
    float4 s = make_float4(0.f, 0.f, 0.f, 0.f);
#pragma unroll
    for (int ks = 0; ks < KSPLIT_; ks++) {
        float4 v = reinterpret_cast<const float4*>(g_p50p)[(long)ks * total + i];
        s.x += v.x; s.y += v.y; s.z += v.z; s.w += v.w;
    }
    reinterpret_cast<float4*>(g_p50)[i] = s;
}

// ---------------------------------------------------------------------------
// Kernel 5: flash attention with mma.sync bf16x3.
// Q tile 128 x 64 per block, 8 warps (warp = 16 q-rows x 64 kv-cols).
// S accumulator fragment is reused directly as the P A-operand for PV.
// ---------------------------------------------------------------------------
namespace {
constexpr int LDF = 72;                      // bf16 elems per smem row
// smem layout (bf16 elems):
constexpr int FO_QH = 0;
constexpr int FO_QL = 128 * LDF;             //  9216
constexpr int FO_KH = 2 * 128 * LDF;         // 18432
constexpr int FO_KL = FO_KH + 64 * LDF;      // 23040
constexpr int FO_VH = FO_KL + 64 * LDF;      // 27648
constexpr int FO_VL = FO_VH + 64 * LDF;      // 32256
constexpr int FSM_TOTAL = (FO_VL + 64 * LDF) * 2;   // 73728 B
}

__global__ void __launch_bounds__(256, 2) flash_mma_kernel(
    const float* __restrict__ dbg, const float* __restrict__ gates,
    float* __restrict__ out)
{
    extern __shared__ __nv_bfloat16 fsm[];
    __nv_bfloat16* sQh = fsm + FO_QH;
    __nv_bfloat16* sQl = fsm + FO_QL;
    __nv_bfloat16* sKh = fsm + FO_KH;
    __nv_bfloat16* sKl = fsm + FO_KL;
    __nv_bfloat16* sVh = fsm + FO_VH;
    __nv_bfloat16* sVl = fsm + FO_VL;

    const int tid  = threadIdx.x;
    const int lane = tid & 31;
    const int wid  = tid >> 5;
    const int q0 = blockIdx.x * 128;
    const int h  = blockIdx.y;
    const int b  = blockIdx.z;
    const float QSC = 0.125f * 1.4426950408889634f;   // 1/sqrt(64) * log2(e)

    // ---- load Q tile (debug + pos), scaled, bf16-split ----
    {
        const int row = tid >> 1, p = q0 + row;
        const int c0 = (tid & 1) * 32;
        if (p < QL_) {
            const int pidx = (p * NPE_) / QL_;
            const float* dq = &dbg[(((long)(b * H_ + h) * QL_) + p) * HD_];
            const float* pp = &g_p50[(long)pidx * E_ + h * HD_];
#pragma unroll
            for (int w8 = 0; w8 < 8; w8++) {
                const int d = c0 + w8 * 4;
                float4 dv = *reinterpret_cast<const float4*>(&dq[d]);
                float4 pv = *reinterpret_cast<const float4*>(&pp[d]);
                float vals[4] = {(dv.x+pv.x)*QSC, (dv.y+pv.y)*QSC,
                                 (dv.z+pv.z)*QSC, (dv.w+pv.w)*QSC};
#pragma unroll
                for (int q = 0; q < 4; q++) {
                    __nv_bfloat16 hh, ll;
                    split_bf16(vals[q], hh, ll);
                    sQh[row * LDF + d + q] = hh;
                    sQl[row * LDF + d + q] = ll;
                }
            }
        } else {
#pragma unroll
            for (int w8 = 0; w8 < 8; w8++) {
                const int d = c0 + w8 * 4;
#pragma unroll
                for (int q = 0; q < 4; q++) {
                    sQh[row * LDF + d + q] = __nv_bfloat16(0.f);
                    sQl[row * LDF + d + q] = __nv_bfloat16(0.f);
                }
            }
        }
    }

    const uint32_t sQh_b = smem_u32(sQh), sQl_b = smem_u32(sQl);
    const uint32_t sKh_b = smem_u32(sKh), sKl_b = smem_u32(sKl);
    const uint32_t sVh_b = smem_u32(sVh), sVl_b = smem_u32(sVl);
    const uint32_t aoff  = ((wid * 16 + (lane & 15)) * LDF + (lane >> 4) * 8) * 2;
    const uint32_t b4off = ((lane & 7) * LDF + ((lane >> 3) & 1) * 8 +
                           ((lane >> 4) & 1) * 8 * LDF) * 2;

    float accO[8][4];
#pragma unroll
    for (int nt = 0; nt < 8; nt++)
#pragma unroll
        for (int q = 0; q < 4; q++) accO[nt][q] = 0.f;
    float mA = -1e30f, mB = -1e30f, lA = 0.f, lB = 0.f;

    __syncthreads();

    for (int t0 = 0; t0 < T_; t0 += 64) {
        const int vk = (T_ - t0 < 64) ? (T_ - t0) : 64;

        // ---- load K (natural) + V (transposed) tiles, bf16-split ----
        {
            const int j = tid >> 2, seg = tid & 3;
            const bool valid = j < vk;
            const float* kr = &g_K[((long)b * T_ + t0 + j) * E_ + h * HD_];
            const float* vr = &g_V[((long)b * T_ + t0 + j) * E_ + h * HD_];
#pragma unroll
            for (int w4 = 0; w4 < 4; w4++) {
                const int d = seg * 16 + w4 * 4;
                float4 kv4 = valid ? *reinterpret_cast<const float4*>(&kr[d])
                                   : make_float4(0.f, 0.f, 0.f, 0.f);
                float4 vv4 = valid ? *reinterpret_cast<const float4*>(&vr[d])
                                   : make_float4(0.f, 0.f, 0.f, 0.f);
                float kvals[4] = {kv4.x, kv4.y, kv4.z, kv4.w};
                float vvals[4] = {vv4.x, vv4.y, vv4.z, vv4.w};
#pragma unroll
                for (int q = 0; q < 4; q++) {
                    __nv_bfloat16 hh, ll;
                    split_bf16(kvals[q], hh, ll);
                    sKh[j * LDF + d + q] = hh;
                    sKl[j * LDF + d + q] = ll;
                    split_bf16(vvals[q], hh, ll);
                    sVh[(d + q) * LDF + j] = hh;   // transposed [d][j]
                    sVl[(d + q) * LDF + j] = ll;
                }
            }
        }
        __syncthreads();

        // ---- QK^T: S = Qh*Kh + Qh*Kl + Ql*Kh (fp32 accum, log2 domain) ----
        float accS[8][4];
#pragma unroll
        for (int nt = 0; nt < 8; nt++)
#pragma unroll
            for (int q = 0; q < 4; q++) accS[nt][q] = 0.f;

#pragma unroll
        for (int ks = 0; ks < 4; ks++) {
            const uint32_t kb = ks * 32;
            uint32_t qh[4], ql[4];
            ldsm_x4(sQh_b + aoff + kb, qh[0], qh[1], qh[2], qh[3]);
            ldsm_x4(sQl_b + aoff + kb, ql[0], ql[1], ql[2], ql[3]);
#pragma unroll
            for (int nt2 = 0; nt2 < 4; nt2++) {
                const uint32_t bo = b4off + nt2 * (16 * LDF * 2) + kb;
                uint32_t bh[4], bl[4];
                ldsm_x4(sKh_b + bo, bh[0], bh[1], bh[2], bh[3]);
                ldsm_x4(sKl_b + bo, bl[0], bl[1], bl[2], bl[3]);
                mma16816(accS[2*nt2],   qh, bh);
                mma16816(accS[2*nt2],   qh, bl);
                mma16816(accS[2*nt2],   ql, bh);
                mma16816(accS[2*nt2+1], qh, bh + 2);
                mma16816(accS[2*nt2+1], qh, bl + 2);
                mma16816(accS[2*nt2+1], ql, bh + 2);
            }
        }

        // ---- online softmax in registers (rows r = lane>>2 and r+8) ----
        {
            float mxA = -1e30f, mxB = -1e30f;
#pragma unroll
            for (int nt = 0; nt < 8; nt++) {
                mxA = fmaxf(mxA, fmaxf(accS[nt][0], accS[nt][1]));
                mxB = fmaxf(mxB, fmaxf(accS[nt][2], accS[nt][3]));
            }
            mxA = fmaxf(mxA, __shfl_xor_sync(0xffffffffu, mxA, 1));
            mxA = fmaxf(mxA, __shfl_xor_sync(0xffffffffu, mxA, 2));
            mxB = fmaxf(mxB, __shfl_xor_sync(0xffffffffu, mxB, 1));
            mxB = fmaxf(mxB, __shfl_xor_sync(0xffffffffu, mxB, 2));
            const float mnA = fmaxf(mA, mxA), mnB = fmaxf(mB, mxB);
            const float corrA = exp2f(mA - mnA), corrB = exp2f(mB - mnB);
            mA = mnA; mB = mnB;

            float sumA = 0.f, sumB = 0.f;
#pragma unroll
            for (int nt = 0; nt < 8; nt++) {
                const int j0 = nt * 8 + (lane & 3) * 2;
                const bool v0 = j0 < vk, v1 = (j0 + 1) < vk;
                accS[nt][0] = v0 ? exp2f(accS[nt][0] - mnA) : 0.f;
                accS[nt][1] = v1 ? exp2f(accS[nt][1] - mnA) : 0.f;
                accS[nt][2] = v0 ? exp2f(accS[nt][2] - mnB) : 0.f;
                accS[nt][3] = v1 ? exp2f(accS[nt][3] - mnB) : 0.f;
                sumA += accS[nt][0] + accS[nt][1];
                sumB += accS[nt][2] + accS[nt][3];
            }
            sumA += __shfl_xor_sync(0xffffffffu, sumA, 1);
            sumA += __shfl_xor_sync(0xffffffffu, sumA, 2);
            sumB += __shfl_xor_sync(0xffffffffu, sumB, 1);
            sumB += __shfl_xor_sync(0xffffffffu, sumB, 2);
            lA = lA * corrA + sumA;
            lB = lB * corrB + sumB;
#pragma unroll
            for (int nt = 0; nt < 8; nt++) {
                accO[nt][0] *= corrA; accO[nt][1] *= corrA;
                accO[nt][2] *= corrB; accO[nt][3] *= corrB;
            }
        }

        // ---- PV: O += Ph*Vh + Ph*Vl + Pl*Vh (P packed from accS regs) ----
#pragma unroll
        for (int ks = 0; ks < 4; ks++) {
            uint32_t ah[4], al[4];
            split_pack(accS[2*ks][0],   accS[2*ks][1],   ah[0], al[0]);
            split_pack(accS[2*ks][2],   accS[2*ks][3],   ah[1], al[1]);
            split_pack(accS[2*ks+1][0], accS[2*ks+1][1], ah[2], al[2]);
            split_pack(accS[2*ks+1][2], accS[2*ks+1][3], ah[3], al[3]);
            const uint32_t kb = ks * 32;
#pragma unroll
            for (int nt2 = 0; nt2 < 4; nt2++) {
                const uint32_t bo = b4off + nt2 * (16 * LDF * 2) + kb;
                uint32_t bh[4], bl[4];
                ldsm_x4(sVh_b + bo, bh[0], bh[1], bh[2], bh[3]);
                ldsm_x4(sVl_b + bo, bl[0], bl[1], bl[2], bl[3]);
                mma16816(accO[2*nt2],   ah, bh);
                mma16816(accO[2*nt2],   ah, bl);
                mma16816(accO[2*nt2],   al, bh);
                mma16816(accO[2*nt2+1], ah, bh + 2);
                mma16816(accO[2*nt2+1], ah, bl + 2);
                mma16816(accO[2*nt2+1], al, bh + 2);
            }
        }
        __syncthreads();
    }

    // ---- epilogue ----
    const float g = gates[0];
    const int r  = wid * 16 + (lane >> 2);
    const int pA = q0 + r, pB = pA + 8;
    const float invA = g / lA, invB = g / lB;
#pragma unroll
    for (int nt = 0; nt < 8; nt++) {
        const int col = h * HD_ + nt * 8 + (lane & 3) * 2;
        if (pA < QL_) {
            *reinterpret_cast<float2*>(&out[((long)b * QL_ + pA) * E_ + col]) =
                make_float2(accO[nt][0] * invA, accO[nt][1] * invA);
        }
        if (pB < QL_) {
            *reinterpret_cast<float2*>(&out[((long)b * QL_ + pB) * E_ + col]) =
                make_float2(accO[nt][2] * invB, accO[nt][3] * invB);
        }
    }
}

// ---------------------------------------------------------------------------
// Launch
// ---------------------------------------------------------------------------
extern "C" void kernel_launch(void* const* d_in, const int* in_sizes, int n_in,
                              void* d_out, int out_size)
{
    const float* x_b    = (const float*)d_in[1];
    const float* dbg    = (const float*)d_in[2];
    const float* Wk     = (const float*)d_in[3];
    const float* Wv     = (const float*)d_in[4];
    const float* Wpos   = (const float*)d_in[5];
    const float* prompt = (const float*)d_in[6];
    const float* gates  = (const float*)d_in[7];
    const float* pe     = (const float*)d_in[8];
    float* out = (float*)d_out;

    // 1) build bf16-split A (kv) and W
    {
        const long total4 = (long)MPAD * (KD_ / 4);
        build_a_bf16_kernel<<<(int)((total4 + 255) / 256), 256>>>(x_b, prompt, pe);
        const long wtotal4 = 2L * KD_ * (KD_ / 4);
        prep_w_kernel<<<(int)((wtotal4 + 255) / 256), 256>>>(Wk, Wv);
    }
    // 2) tensor-core K/V projections (bf16x3, pipelined)
    {
        cudaFuncSetAttribute(gemm_mma_kernel, cudaFuncAttributeMaxDynamicSharedMemorySize, GSM2_TOTAL);
        dim3 g(MPAD / 128, E_ / 128, 2);
        gemm_mma_kernel<<<g, 256, GSM2_TOTAL>>>();
    }
    // 3) tiny pos GEMM
    {
        dim3 g(E_ / 64, KSPLIT_);
        gemm_pos_kernel<<<g, 256>>>(pe, Wpos);
        const int total4 = NPE_ * (E_ / 4);
        reduce_pos_kernel<<<(total4 + 255) / 256, 256>>>();
    }
    // 4) flash attention (mma.sync bf16x3)
    {
        cudaFuncSetAttribute(flash_mma_kernel, cudaFuncAttributeMaxDynamicSharedMemorySize, FSM_TOTAL);
        dim3 g((QL_ + 127) / 128, H_, B_);
        flash_mma_kernel<<<g, 256, FSM_TOTAL>>>(dbg, gates, out);
    }
}

// round 6
// speedup vs baseline: 3.0563x; 1.1981x over previous
#include <cuda_runtime.h>
#include <cuda_bf16.h>
#include <math.h>
#include <stdint.h>

// ---------------------------------------------------------------------------
// Problem constants (B=4, T_B=2048, Q_LEN=801)
// ---------------------------------------------------------------------------
namespace {
constexpr int B_   = 4;
constexpr int H_   = 16;
constexpr int HD_  = 64;
constexpr int E_   = 1024;
constexpr int QL_  = 801;
constexpr int TB_  = 2048;
constexpr int T_   = 2049;
constexpr int KD_  = 1024;
constexpr int NPE_ = 50;
constexpr int KSPLIT_ = 8;
constexpr int M_KV  = B_ * T_;           // 8196
constexpr int MPAD  = 8320;              // 65 * 128
}

// ---------------------------------------------------------------------------
// Device scratch
// ---------------------------------------------------------------------------
__device__ float g_p50[(size_t)NPE_ * E_];
__device__ float g_p50p[(size_t)KSPLIT_ * NPE_ * E_];
__device__ __nv_bfloat16 g_Ah[(size_t)MPAD * KD_];
__device__ __nv_bfloat16 g_Al[(size_t)MPAD * KD_];
__device__ __nv_bfloat16 g_Wh[(size_t)2 * KD_ * KD_];
__device__ __nv_bfloat16 g_Wl[(size_t)2 * KD_ * KD_];
__device__ __nv_bfloat16 g_Kh[(size_t)M_KV * E_];
__device__ __nv_bfloat16 g_Kl[(size_t)M_KV * E_];
__device__ __nv_bfloat16 g_Vh[(size_t)M_KV * E_];
__device__ __nv_bfloat16 g_Vl[(size_t)M_KV * E_];

// ---------------------------------------------------------------------------
// Helpers (family-portable: cp.async, ldmatrix, mma.sync)
// ---------------------------------------------------------------------------
__device__ __forceinline__ uint32_t smem_u32(const void* p) {
    uint32_t a;
    asm("{ .reg .u64 t; cvta.to.shared.u64 t, %1; cvt.u32.u64 %0, t; }" : "=r"(a) : "l"(p));
    return a;
}
__device__ __forceinline__ void cp_async16(uint32_t dst, const void* src) {
    asm volatile("cp.async.cg.shared.global [%0], [%1], 16;" :: "r"(dst), "l"(src));
}
__device__ __forceinline__ void cp_async16z(uint32_t dst, const void* src, uint32_t sz) {
    asm volatile("cp.async.cg.shared.global [%0], [%1], 16, %2;" :: "r"(dst), "l"(src), "r"(sz));
}
#define CP_COMMIT()  asm volatile("cp.async.commit_group;" ::: "memory")
#define CP_WAIT0()   asm volatile("cp.async.wait_group 0;" ::: "memory")
#define CP_WAIT1()   asm volatile("cp.async.wait_group 1;" ::: "memory")

__device__ __forceinline__ void ldsm_x4(uint32_t a, uint32_t& r0, uint32_t& r1,
                                        uint32_t& r2, uint32_t& r3) {
    asm volatile("ldmatrix.sync.aligned.m8n8.x4.shared.b16 {%0,%1,%2,%3}, [%4];"
                 : "=r"(r0), "=r"(r1), "=r"(r2), "=r"(r3) : "r"(a));
}
__device__ __forceinline__ void ldsm_x4t(uint32_t a, uint32_t& r0, uint32_t& r1,
                                         uint32_t& r2, uint32_t& r3) {
    asm volatile("ldmatrix.sync.aligned.m8n8.x4.trans.shared.b16 {%0,%1,%2,%3}, [%4];"
                 : "=r"(r0), "=r"(r1), "=r"(r2), "=r"(r3) : "r"(a));
}
__device__ __forceinline__ void mma16816(float* d, const uint32_t* a, const uint32_t* b) {
    asm volatile(
        "mma.sync.aligned.m16n8k16.row.col.f32.bf16.bf16.f32 "
        "{%0,%1,%2,%3}, {%4,%5,%6,%7}, {%8,%9}, {%0,%1,%2,%3};"
        : "+f"(d[0]), "+f"(d[1]), "+f"(d[2]), "+f"(d[3])
        : "r"(a[0]), "r"(a[1]), "r"(a[2]), "r"(a[3]), "r"(b[0]), "r"(b[1]));
}
__device__ __forceinline__ void split_bf16(float x, __nv_bfloat16& h, __nv_bfloat16& l) {
    h = __float2bfloat16(x);
    l = __float2bfloat16(x - __bfloat162float(h));
}
// pack two fp32 -> bf16x2 (hi) + residual bf16x2 (lo)
__device__ __forceinline__ void split_pack(float p0, float p1, uint32_t& hp, uint32_t& lp) {
    __nv_bfloat162 hv = __floats2bfloat162_rn(p0, p1);
    hp = *reinterpret_cast<uint32_t*>(&hv);
    float h0 = __bfloat162float(hv.x);
    float h1 = __bfloat162float(hv.y);
    __nv_bfloat162 lv = __floats2bfloat162_rn(p0 - h0, p1 - h1);
    lp = *reinterpret_cast<uint32_t*>(&lv);
}

// ---------------------------------------------------------------------------
// Kernel 1: build kv as (hi, lo) bf16 split, padded to MPAD rows.
// ---------------------------------------------------------------------------
__global__ void __launch_bounds__(256) build_a_bf16_kernel(
    const float* __restrict__ xb, const float* __restrict__ prompt,
    const float* __restrict__ pe)
{
    long i = (long)blockIdx.x * 256 + threadIdx.x;
    const long total = (long)MPAD * (KD_ / 4);
    if (i >= total) return;
    int  c4 = (int)(i & 255);
    long bt = i >> 8;
    float4 v = make_float4(0.f, 0.f, 0.f, 0.f);
    if (bt < M_KV) {
        int t = (int)(bt % T_);
        int b = (int)(bt / T_);
        if (t == 0) {
            v = reinterpret_cast<const float4*>(prompt)[c4];
        } else {
            float4 x = reinterpret_cast<const float4*>(xb)[((long)b * TB_ + (t - 1)) * 256 + c4];
            float4 p = reinterpret_cast<const float4*>(pe)[(long)(t - 1) * 256 + c4];
            v.x = x.x + p.x; v.y = x.y + p.y; v.z = x.z + p.z; v.w = x.w + p.w;
        }
    }
    __nv_bfloat16 h[4], l[4];
    split_bf16(v.x, h[0], l[0]); split_bf16(v.y, h[1], l[1]);
    split_bf16(v.z, h[2], l[2]); split_bf16(v.w, h[3], l[3]);
    __nv_bfloat162* Hp = reinterpret_cast<__nv_bfloat162*>(g_Ah);
    __nv_bfloat162* Lp = reinterpret_cast<__nv_bfloat162*>(g_Al);
    Hp[i * 2 + 0] = __nv_bfloat162(h[0], h[1]);
    Hp[i * 2 + 1] = __nv_bfloat162(h[2], h[3]);
    Lp[i * 2 + 0] = __nv_bfloat162(l[0], l[1]);
    Lp[i * 2 + 1] = __nv_bfloat162(l[2], l[3]);
}

// ---------------------------------------------------------------------------
// Kernel 2: split Wk / Wv into bf16 (hi, lo)
// ---------------------------------------------------------------------------
__global__ void __launch_bounds__(256) prep_w_kernel(
    const float* __restrict__ Wk, const float* __restrict__ Wv)
{
    long i = (long)blockIdx.x * 256 + threadIdx.x;
    const long total = 2L * KD_ * (KD_ / 4);
    if (i >= total) return;
    int  w = (int)(i >> 18);
    long j = i & 0x3FFFF;
    const float4 v = reinterpret_cast<const float4*>(w ? Wv : Wk)[j];
    __nv_bfloat16 h[4], l[4];
    split_bf16(v.x, h[0], l[0]); split_bf16(v.y, h[1], l[1]);
    split_bf16(v.z, h[2], l[2]); split_bf16(v.w, h[3], l[3]);
    __nv_bfloat162* Hp = reinterpret_cast<__nv_bfloat162*>(g_Wh);
    __nv_bfloat162* Lp = reinterpret_cast<__nv_bfloat162*>(g_Wl);
    Hp[i * 2 + 0] = __nv_bfloat162(h[0], h[1]);
    Hp[i * 2 + 1] = __nv_bfloat162(h[2], h[3]);
    Lp[i * 2 + 0] = __nv_bfloat162(l[0], l[1]);
    Lp[i * 2 + 1] = __nv_bfloat162(l[2], l[3]);
}

// ---------------------------------------------------------------------------
// Kernel 3: mma.sync bf16x3 NT GEMM, 2-stage pipeline; epilogue writes bf16
// hi/lo splits of K/V directly.
// ---------------------------------------------------------------------------
namespace {
constexpr int LDT2   = 40;
constexpr int PTILE  = 128 * LDT2;
constexpr int PSTAGE = 4 * PTILE;
constexpr int GSM2_TOTAL = 2 * PSTAGE * 2;   // 81920 B
constexpr int BKC2 = 32;
constexpr int NCH2 = KD_ / BKC2;             // 32
}

__global__ void __launch_bounds__(256, 2) gemm_mma_kernel()
{
    extern __shared__ __nv_bfloat16 ps[];
    const uint32_t smb = smem_u32(ps);

    const int tid  = threadIdx.x;
    const int lane = tid & 31;
    const int wid  = tid >> 5;
    const int wm   = wid >> 2;
    const int wn   = wid & 3;
    const int m0   = blockIdx.x * 128;
    const int n0   = blockIdx.y * 128;
    const int w    = blockIdx.z;

    const __nv_bfloat16* srcs[4] = {
        g_Ah + (long)m0 * KD_,
        g_Al + (long)m0 * KD_,
        g_Wh + ((long)w << 20) + (long)n0 * KD_,
        g_Wl + ((long)w << 20) + (long)n0 * KD_ };

    const int cprow0 = tid >> 2, cpseg0 = tid & 3;
    const int cprow1 = (256 + tid) >> 2, cpseg1 = (256 + tid) & 3;

    const uint32_t aoff  = ((wm * 64 + (lane & 15)) * LDT2 + (lane >> 4) * 8) * 2;
    const uint32_t b4off = ((lane & 7) * LDT2 + ((lane >> 3) & 1) * 8 +
                           ((lane >> 4) & 1) * 8 * LDT2) * 2 + wn * (32 * LDT2 * 2);

    float acc[4][4][4];
#pragma unroll
    for (int i = 0; i < 4; i++)
#pragma unroll
        for (int j = 0; j < 4; j++)
#pragma unroll
            for (int q = 0; q < 4; q++) acc[i][j][q] = 0.f;

    auto issue = [&](int c, int s) {
        const uint32_t sb = smb + (uint32_t)(s * PSTAGE) * 2;
#pragma unroll
        for (int tl = 0; tl < 4; tl++) {
            const uint32_t tb = sb + (uint32_t)(tl * PTILE) * 2;
            cp_async16(tb + cprow0 * (LDT2 * 2) + cpseg0 * 16,
                       srcs[tl] + (long)cprow0 * KD_ + c * BKC2 + cpseg0 * 8);
            cp_async16(tb + cprow1 * (LDT2 * 2) + cpseg1 * 16,
                       srcs[tl] + (long)cprow1 * KD_ + c * BKC2 + cpseg1 * 8);
        }
    };

    issue(0, 0);
    CP_COMMIT();

    for (int c = 0; c < NCH2; c++) {
        const int s = c & 1;
        const bool more = (c + 1 < NCH2);
        if (more) { issue(c + 1, (c + 1) & 1); CP_COMMIT(); CP_WAIT1(); }
        else      { CP_WAIT0(); }
        __syncthreads();

        const uint32_t sA_h = smb + (uint32_t)(s * PSTAGE + 0 * PTILE) * 2;
        const uint32_t sA_l = smb + (uint32_t)(s * PSTAGE + 1 * PTILE) * 2;
        const uint32_t sB_h = smb + (uint32_t)(s * PSTAGE + 2 * PTILE) * 2;
        const uint32_t sB_l = smb + (uint32_t)(s * PSTAGE + 3 * PTILE) * 2;

#pragma unroll
        for (int ks = 0; ks < 2; ks++) {
            const uint32_t kb = ks * 32;
            uint32_t bh[2][4], bl[2][4];
#pragma unroll
            for (int nt2 = 0; nt2 < 2; nt2++) {
                const uint32_t bo = b4off + nt2 * (16 * LDT2 * 2) + kb;
                ldsm_x4(sB_h + bo, bh[nt2][0], bh[nt2][1], bh[nt2][2], bh[nt2][3]);
                ldsm_x4(sB_l + bo, bl[nt2][0], bl[nt2][1], bl[nt2][2], bl[nt2][3]);
            }
#pragma unroll
            for (int mt = 0; mt < 4; mt++) {
                const uint32_t ao = aoff + mt * (16 * LDT2 * 2) + kb;
                uint32_t ah[4], al[4];
                ldsm_x4(sA_h + ao, ah[0], ah[1], ah[2], ah[3]);
                ldsm_x4(sA_l + ao, al[0], al[1], al[2], al[3]);
#pragma unroll
                for (int nt2 = 0; nt2 < 2; nt2++) {
                    mma16816(acc[mt][2*nt2],   ah, bh[nt2]);
                    mma16816(acc[mt][2*nt2],   ah, bl[nt2]);
                    mma16816(acc[mt][2*nt2],   al, bh[nt2]);
                    mma16816(acc[mt][2*nt2+1], ah, bh[nt2] + 2);
                    mma16816(acc[mt][2*nt2+1], ah, bl[nt2] + 2);
                    mma16816(acc[mt][2*nt2+1], al, bh[nt2] + 2);
                }
            }
        }
        __syncthreads();
    }

    // epilogue: split fp32 accum into bf16 hi/lo and store packed pairs
    __nv_bfloat16* Ch = w ? g_Vh : g_Kh;
    __nv_bfloat16* Cl = w ? g_Vl : g_Kl;
    const int r0 = lane >> 2;
    const int cc = (lane & 3) * 2;
#pragma unroll
    for (int mt = 0; mt < 4; mt++) {
#pragma unroll
        for (int nt = 0; nt < 4; nt++) {
            const int mA = m0 + wm * 64 + mt * 16 + r0;
            const int nn = n0 + wn * 32 + nt * 8 + cc;
            uint32_t hp, lp;
            if (mA < M_KV) {
                split_pack(acc[mt][nt][0], acc[mt][nt][1], hp, lp);
                *reinterpret_cast<uint32_t*>(&Ch[(long)mA * E_ + nn]) = hp;
                *reinterpret_cast<uint32_t*>(&Cl[(long)mA * E_ + nn]) = lp;
            }
            if (mA + 8 < M_KV) {
                split_pack(acc[mt][nt][2], acc[mt][nt][3], hp, lp);
                *reinterpret_cast<uint32_t*>(&Ch[(long)(mA + 8) * E_ + nn]) = hp;
                *reinterpret_cast<uint32_t*>(&Cl[(long)(mA + 8) * E_ + nn]) = lp;
            }
        }
    }
}

// ---------------------------------------------------------------------------
// Kernel 4: tiny pos GEMM (k-split) + reduce (~12us, unchanged)
// ---------------------------------------------------------------------------
__global__ void __launch_bounds__(256) gemm_pos_kernel(
    const float* __restrict__ pe, const float* __restrict__ Wpos)
{
    constexpr int BK = 16, KS = KD_ / KSPLIT_;
    __shared__ float As[BK][64 + 4];
    __shared__ float Ws[BK][64 + 4];
    const int tid  = threadIdx.x;
    const int tx   = tid & 15, ty = tid >> 4;
    const int lrow = tid >> 2, lseg = tid & 3;
    const int n0   = blockIdx.x * 64;
    const int k0   = blockIdx.y * KS;

    float acc[4][4] = {};
    for (int c0 = k0; c0 < k0 + KS; c0 += BK) {
        const int cc = c0 + lseg * 4;
        float4 a = make_float4(0.f, 0.f, 0.f, 0.f);
        if (lrow < NPE_) a = *reinterpret_cast<const float4*>(&pe[(long)lrow * KD_ + cc]);
        float4 w = *reinterpret_cast<const float4*>(&Wpos[(long)(n0 + lrow) * KD_ + cc]);
        __syncthreads();
        As[lseg*4+0][lrow] = a.x; As[lseg*4+1][lrow] = a.y;
        As[lseg*4+2][lrow] = a.z; As[lseg*4+3][lrow] = a.w;
        Ws[lseg*4+0][lrow] = w.x; Ws[lseg*4+1][lrow] = w.y;
        Ws[lseg*4+2][lrow] = w.z; Ws[lseg*4+3][lrow] = w.w;
        __syncthreads();
#pragma unroll
        for (int kk = 0; kk < BK; kk++) {
            float4 a4 = *reinterpret_cast<const float4*>(&As[kk][ty * 4]);
            float4 w4 = *reinterpret_cast<const float4*>(&Ws[kk][tx * 4]);
            acc[0][0] += a4.x*w4.x; acc[0][1] += a4.x*w4.y; acc[0][2] += a4.x*w4.z; acc[0][3] += a4.x*w4.w;
            acc[1][0] += a4.y*w4.x; acc[1][1] += a4.y*w4.y; acc[1][2] += a4.y*w4.z; acc[1][3] += a4.y*w4.w;
            acc[2][0] += a4.z*w4.x; acc[2][1] += a4.z*w4.y; acc[2][2] += a4.z*w4.z; acc[2][3] += a4.z*w4.w;
            acc[3][0] += a4.w*w4.x; acc[3][1] += a4.w*w4.y; acc[3][2] += a4.w*w4.z; acc[3][3] += a4.w*w4.w;
        }
    }
#pragma unroll
    for (int ii = 0; ii < 4; ii++) {
        int m = ty * 4 + ii;
        if (m < NPE_) {
            *reinterpret_cast<float4*>(
                &g_p50p[((long)blockIdx.y * NPE_ + m) * E_ + n0 + tx * 4]) =
                make_float4(acc[ii][0], acc[ii][1], acc[ii][2], acc[ii][3]);
        }
    }
}

__global__ void __launch_bounds__(256) reduce_pos_kernel() {
    int i = blockIdx.x * 256 + threadIdx.x;
    const int total = NPE_ * (E_ / 4);
    if (i >= total) return;
    float4 s = make_float4(0.f, 0.f, 0.f, 0.f);
#pragma unroll
    for (int ks = 0; ks < KSPLIT_; ks++) {
        float4 v = reinterpret_cast<const float4*>(g_p50p)[(long)ks * total + i];
        s.x += v.x; s.y += v.y; s.z += v.z; s.w += v.w;
    }
    reinterpret_cast<float4*>(g_p50)[i] = s;
}

// ---------------------------------------------------------------------------
// Kernel 5: flash attention, mma.sync bf16x3, double-buffered cp.async K/V
// loads from pre-split bf16, V via ldmatrix.trans (no transposed smem store).
// ---------------------------------------------------------------------------
namespace {
constexpr int LDF   = 72;                        // bf16 elems per smem row
constexpr int FQ_H  = 0;                         // elem offsets
constexpr int FQ_L  = 128 * LDF;
constexpr int FSTG0 = 2 * 128 * LDF;             // K/V stage area start
constexpr int FTILE = 64 * LDF;                  // elems per K/V tile
constexpr int FSTG  = 4 * FTILE;                 // elems per stage (Kh,Kl,Vh,Vl)
constexpr int FSM_TOTAL = (FSTG0 + 2 * FSTG) * 2;  // 110592 B
constexpr int NT_TILES = (T_ + 63) / 64;         // 33
}

__global__ void __launch_bounds__(256, 2) flash_mma_kernel(
    const float* __restrict__ dbg, const float* __restrict__ gates,
    float* __restrict__ out)
{
    extern __shared__ __nv_bfloat16 fsm[];
    const uint32_t smb = smem_u32(fsm);

    const int tid  = threadIdx.x;
    const int lane = tid & 31;
    const int wid  = tid >> 5;
    const int q0 = blockIdx.x * 128;
    const int h  = blockIdx.y;
    const int b  = blockIdx.z;
    const float QSC = 0.125f * 1.4426950408889634f;   // 1/sqrt(64) * log2(e)

    // ---- load Q tile (debug + pos), scaled, bf16-split (once) ----
    {
        __nv_bfloat16* sQh = fsm + FQ_H;
        __nv_bfloat16* sQl = fsm + FQ_L;
        const int row = tid >> 1, p = q0 + row;
        const int c0 = (tid & 1) * 32;
        if (p < QL_) {
            const int pidx = (p * NPE_) / QL_;
            const float* dq = &dbg[(((long)(b * H_ + h) * QL_) + p) * HD_];
            const float* pp = &g_p50[(long)pidx * E_ + h * HD_];
#pragma unroll
            for (int w8 = 0; w8 < 8; w8++) {
                const int d = c0 + w8 * 4;
                float4 dv = *reinterpret_cast<const float4*>(&dq[d]);
                float4 pv = *reinterpret_cast<const float4*>(&pp[d]);
                float vals[4] = {(dv.x+pv.x)*QSC, (dv.y+pv.y)*QSC,
                                 (dv.z+pv.z)*QSC, (dv.w+pv.w)*QSC};
#pragma unroll
                for (int q = 0; q < 4; q++) {
                    __nv_bfloat16 hh, ll;
                    split_bf16(vals[q], hh, ll);
                    sQh[row * LDF + d + q] = hh;
                    sQl[row * LDF + d + q] = ll;
                }
            }
        } else {
#pragma unroll
            for (int w8 = 0; w8 < 8; w8++) {
                const int d = c0 + w8 * 4;
#pragma unroll
                for (int q = 0; q < 4; q++) {
                    sQh[row * LDF + d + q] = __nv_bfloat16(0.f);
                    sQl[row * LDF + d + q] = __nv_bfloat16(0.f);
                }
            }
        }
    }

    const uint32_t sQh_b = smb + FQ_H * 2;
    const uint32_t sQl_b = smb + FQ_L * 2;
    const uint32_t aoff  = ((wid * 16 + (lane & 15)) * LDF + (lane >> 4) * 8) * 2;
    // K (non-trans B): j in cols-of-B sense
    const uint32_t b4off = ((lane & 7) * LDF + ((lane >> 3) & 1) * 8 +
                           ((lane >> 4) & 1) * 8 * LDF) * 2;
    // V (trans B): k=j rows, n=d cols
    const uint32_t v4off = ((lane & 15) * LDF + ((lane >> 4) & 1) * 8) * 2;

    const __nv_bfloat16* fsrcs[4] = {g_Kh, g_Kl, g_Vh, g_Vl};

    // cp.async loader: 8 ops/thread covering 4 tiles x 64 rows x 8 segs
    auto issueF = [&](int ti, int s) {
        const int t0 = ti * 64;
        const uint32_t sb = smb + (uint32_t)(FSTG0 + s * FSTG) * 2;
#pragma unroll
        for (int q = 0; q < 8; q++) {
            const int idx = q * 256 + tid;
            const int tl = idx >> 9, row = (idx >> 3) & 63, seg = idx & 7;
            const int t = t0 + row;
            const int tc = (t < T_) ? t : (T_ - 1);
            const __nv_bfloat16* gp = fsrcs[tl] + ((long)b * T_ + tc) * E_ + h * HD_ + seg * 8;
            const uint32_t dst = sb + (uint32_t)(tl * FTILE) * 2 + row * (LDF * 2) + seg * 16;
            cp_async16z(dst, gp, (t < T_) ? 16u : 0u);
        }
    };

    float accO[8][4];
#pragma unroll
    for (int nt = 0; nt < 8; nt++)
#pragma unroll
        for (int q = 0; q < 4; q++) accO[nt][q] = 0.f;
    float mA = -1e30f, mB = -1e30f, lA = 0.f, lB = 0.f;

    issueF(0, 0);
    CP_COMMIT();

    for (int ti = 0; ti < NT_TILES; ti++) {
        const int vk = (T_ - ti * 64 < 64) ? (T_ - ti * 64) : 64;
        const bool more = (ti + 1 < NT_TILES);
        if (more) { issueF(ti + 1, (ti + 1) & 1); CP_COMMIT(); CP_WAIT1(); }
        else      { CP_WAIT0(); }
        __syncthreads();

        const uint32_t sb = smb + (uint32_t)(FSTG0 + (ti & 1) * FSTG) * 2;
        const uint32_t sKh_b = sb;
        const uint32_t sKl_b = sb + (uint32_t)FTILE * 2;
        const uint32_t sVh_b = sb + (uint32_t)(2 * FTILE) * 2;
        const uint32_t sVl_b = sb + (uint32_t)(3 * FTILE) * 2;

        // ---- QK^T: S = Qh*Kh + Qh*Kl + Ql*Kh ----
        float accS[8][4];
#pragma unroll
        for (int nt = 0; nt < 8; nt++)
#pragma unroll
            for (int q = 0; q < 4; q++) accS[nt][q] = 0.f;

#pragma unroll
        for (int ks = 0; ks < 4; ks++) {
            const uint32_t kb = ks * 32;
            uint32_t qh[4], ql[4];
            ldsm_x4(sQh_b + aoff + kb, qh[0], qh[1], qh[2], qh[3]);
            ldsm_x4(sQl_b + aoff + kb, ql[0], ql[1], ql[2], ql[3]);
#pragma unroll
            for (int nt2 = 0; nt2 < 4; nt2++) {
                const uint32_t bo = b4off + nt2 * (16 * LDF * 2) + kb;
                uint32_t bh[4], bl[4];
                ldsm_x4(sKh_b + bo, bh[0], bh[1], bh[2], bh[3]);
                ldsm_x4(sKl_b + bo, bl[0], bl[1], bl[2], bl[3]);
                mma16816(accS[2*nt2],   qh, bh);
                mma16816(accS[2*nt2],   qh, bl);
                mma16816(accS[2*nt2],   ql, bh);
                mma16816(accS[2*nt2+1], qh, bh + 2);
                mma16816(accS[2*nt2+1], qh, bl + 2);
                mma16816(accS[2*nt2+1], ql, bh + 2);
            }
        }

        // ---- online softmax in registers ----
        {
            float mxA = -1e30f, mxB = -1e30f;
#pragma unroll
            for (int nt = 0; nt < 8; nt++) {
                const int j0 = nt * 8 + (lane & 3) * 2;
                if (j0 < vk) {
                    mxA = fmaxf(mxA, accS[nt][0]);
                    mxB = fmaxf(mxB, accS[nt][2]);
                }
                if (j0 + 1 < vk) {
                    mxA = fmaxf(mxA, accS[nt][1]);
                    mxB = fmaxf(mxB, accS[nt][3]);
                }
            }
            mxA = fmaxf(mxA, __shfl_xor_sync(0xffffffffu, mxA, 1));
            mxA = fmaxf(mxA, __shfl_xor_sync(0xffffffffu, mxA, 2));
            mxB = fmaxf(mxB, __shfl_xor_sync(0xffffffffu, mxB, 1));
            mxB = fmaxf(mxB, __shfl_xor_sync(0xffffffffu, mxB, 2));
            const float mnA = fmaxf(mA, mxA), mnB = fmaxf(mB, mxB);
            const float corrA = exp2f(mA - mnA), corrB = exp2f(mB - mnB);
            mA = mnA; mB = mnB;

            float sumA = 0.f, sumB = 0.f;
#pragma unroll
            for (int nt = 0; nt < 8; nt++) {
                const int j0 = nt * 8 + (lane & 3) * 2;
                const bool v0 = j0 < vk, v1 = (j0 + 1) < vk;
                accS[nt][0] = v0 ? exp2f(accS[nt][0] - mnA) : 0.f;
                accS[nt][1] = v1 ? exp2f(accS[nt][1] - mnA) : 0.f;
                accS[nt][2] = v0 ? exp2f(accS[nt][2] - mnB) : 0.f;
                accS[nt][3] = v1 ? exp2f(accS[nt][3] - mnB) : 0.f;
                sumA += accS[nt][0] + accS[nt][1];
                sumB += accS[nt][2] + accS[nt][3];
            }
            sumA += __shfl_xor_sync(0xffffffffu, sumA, 1);
            sumA += __shfl_xor_sync(0xffffffffu, sumA, 2);
            sumB += __shfl_xor_sync(0xffffffffu, sumB, 1);
            sumB += __shfl_xor_sync(0xffffffffu, sumB, 2);
            lA = lA * corrA + sumA;
            lB = lB * corrB + sumB;
#pragma unroll
            for (int nt = 0; nt < 8; nt++) {
                accO[nt][0] *= corrA; accO[nt][1] *= corrA;
                accO[nt][2] *= corrB; accO[nt][3] *= corrB;
            }
        }

        // ---- PV: O += Ph*Vh + Ph*Vl + Pl*Vh  (V via ldmatrix.trans) ----
#pragma unroll
        for (int ks = 0; ks < 4; ks++) {
            uint32_t ah[4], al[4];
            split_pack(accS[2*ks][0],   accS[2*ks][1],   ah[0], al[0]);
            split_pack(accS[2*ks][2],   accS[2*ks][3],   ah[1], al[1]);
            split_pack(accS[2*ks+1][0], accS[2*ks+1][1], ah[2], al[2]);
            split_pack(accS[2*ks+1][2], accS[2*ks+1][3], ah[3], al[3]);
            const uint32_t ko = ks * (16 * LDF * 2);      // j-block offset
#pragma unroll
            for (int nt2 = 0; nt2 < 4; nt2++) {
                const uint32_t vo = v4off + ko + nt2 * 32; // d-block offset
                uint32_t bh[4], bl[4];
                ldsm_x4t(sVh_b + vo, bh[0], bh[1], bh[2], bh[3]);
                ldsm_x4t(sVl_b + vo, bl[0], bl[1], bl[2], bl[3]);
                mma16816(accO[2*nt2],   ah, bh);
                mma16816(accO[2*nt2],   ah, bl);
                mma16816(accO[2*nt2],   al, bh);
                mma16816(accO[2*nt2+1], ah, bh + 2);
                mma16816(accO[2*nt2+1], ah, bl + 2);
                mma16816(accO[2*nt2+1], al, bh + 2);
            }
        }
        __syncthreads();
    }

    // ---- epilogue ----
    const float g = gates[0];
    const int r  = wid * 16 + (lane >> 2);
    const int pA = q0 + r, pB = pA + 8;
    const float invA = g / lA, invB = g / lB;
#pragma unroll
    for (int nt = 0; nt < 8; nt++) {
        const int col = h * HD_ + nt * 8 + (lane & 3) * 2;
        if (pA < QL_) {
            *reinterpret_cast<float2*>(&out[((long)b * QL_ + pA) * E_ + col]) =
                make_float2(accO[nt][0] * invA, accO[nt][1] * invA);
        }
        if (pB < QL_) {
            *reinterpret_cast<float2*>(&out[((long)b * QL_ + pB) * E_ + col]) =
                make_float2(accO[nt][2] * invB, accO[nt][3] * invB);
        }
    }
}

// ---------------------------------------------------------------------------
// Launch
// ---------------------------------------------------------------------------
extern "C" void kernel_launch(void* const* d_in, const int* in_sizes, int n_in,
                              void* d_out, int out_size)
{
    const float* x_b    = (const float*)d_in[1];
    const float* dbg    = (const float*)d_in[2];
    const float* Wk     = (const float*)d_in[3];
    const float* Wv     = (const float*)d_in[4];
    const float* Wpos   = (const float*)d_in[5];
    const float* prompt = (const float*)d_in[6];
    const float* gates  = (const float*)d_in[7];
    const float* pe     = (const float*)d_in[8];
    float* out = (float*)d_out;

    // 1) build bf16-split A (kv) and W
    {
        const long total4 = (long)MPAD * (KD_ / 4);
        build_a_bf16_kernel<<<(int)((total4 + 255) / 256), 256>>>(x_b, prompt, pe);
        const long wtotal4 = 2L * KD_ * (KD_ / 4);
        prep_w_kernel<<<(int)((wtotal4 + 255) / 256), 256>>>(Wk, Wv);
    }
    // 2) tensor-core K/V projections -> bf16 hi/lo splits
    {
        cudaFuncSetAttribute(gemm_mma_kernel, cudaFuncAttributeMaxDynamicSharedMemorySize, GSM2_TOTAL);
        dim3 g(MPAD / 128, E_ / 128, 2);
        gemm_mma_kernel<<<g, 256, GSM2_TOTAL>>>();
    }
    // 3) tiny pos GEMM
    {
        dim3 g(E_ / 64, KSPLIT_);
        gemm_pos_kernel<<<g, 256>>>(pe, Wpos);
        const int total4 = NPE_ * (E_ / 4);
        reduce_pos_kernel<<<(total4 + 255) / 256, 256>>>();
    }
    // 4) flash attention (mma.sync bf16x3, double-buffered loads)
    {
        cudaFuncSetAttribute(flash_mma_kernel, cudaFuncAttributeMaxDynamicSharedMemorySize, FSM_TOTAL);
        dim3 g((QL_ + 127) / 128, H_, B_);
        flash_mma_kernel<<<g, 256, FSM_TOTAL>>>(dbg, gates, out);
    }
}